// round 7
// baseline (speedup 1.0000x reference)
#include <cuda_runtime.h>
#include <cstdint>

// ---------------------------------------------------------------------------
// HybridSigLSTM: rolling signature + 2-layer LSTM(H=50) + MLP head + pd clip
// B=4096, S=256, DIN=4, WIN=5, D_AUG=5, SIG=30, COMB=35, GATES=4*50=200
// ---------------------------------------------------------------------------

#define B_TOT 4096
#define S_LEN 256
#define GATES 200
#define BT    28      // batch elements per CTA in recurrent kernel
#define NT    256     // threads in recurrent kernel

typedef unsigned long long u64;

// scratch (device global: allocation-free rule)
__device__ float g_pre0[(size_t)B_TOT * S_LEN * 200];  // [t][b][o]

// ---------------- helpers ----------------
__device__ __forceinline__ u64 ffma2(u64 a, u64 b, u64 c) {
    u64 d;
    asm("fma.rn.f32x2 %0, %1, %2, %3;" : "=l"(d) : "l"(a), "l"(b), "l"(c));
    return d;
}
__device__ __forceinline__ u64 pack2(float a, float b) {
    u64 r;
    asm("mov.b64 %0, {%1, %2};" : "=l"(r) : "f"(a), "f"(b));
    return r;
}
__device__ __forceinline__ float2 unpack2(u64 v) {
    float2 f;
    asm("mov.b64 {%0, %1}, %2;" : "=f"(f.x), "=f"(f.y) : "l"(v));
    return f;
}
__device__ __forceinline__ float ex2f(float x) {
    float y; asm("ex2.approx.f32 %0, %1;" : "=f"(y) : "f"(x)); return y;
}
__device__ __forceinline__ float rcpf(float x) {
    float y; asm("rcp.approx.f32 %0, %1;" : "=f"(y) : "f"(x)); return y;
}
__device__ __forceinline__ float sigf(float x) {
    return rcpf(1.0f + ex2f(-1.4426950408889634f * x));
}
__device__ __forceinline__ float tanha(float x) {
    return 2.0f * rcpf(1.0f + ex2f(-2.8853900817779268f * x)) - 1.0f;
}
__device__ __forceinline__ void cpasync16(uint32_t saddr, const void* gptr) {
    asm volatile("cp.async.cg.shared.global [%0], [%1], 16;" :: "r"(saddr), "l"(gptr));
}
__device__ __forceinline__ void cpcommit() {
    asm volatile("cp.async.commit_group;" ::: "memory");
}
__device__ __forceinline__ void cpwait0() {
    asm volatile("cp.async.wait_group 0;" ::: "memory");
}

// ---------------------------------------------------------------------------
// K1: fused signature + input projection (unchanged from R6).
// ---------------------------------------------------------------------------
__global__ __launch_bounds__(256) void pre0f_kernel(const float* __restrict__ features,
                                                    const float* __restrict__ w_ih0,
                                                    const float* __restrict__ b_ih0,
                                                    const float* __restrict__ b_hh0) {
    __shared__ __align__(16) float4 sf[68];        // raw feature window
    __shared__ __align__(16) float xs[64][36];
    const int tid = threadIdx.x;
    const int b   = blockIdx.x >> 2;
    const int t0  = (blockIdx.x & 3) << 6;

    if (tid < 68) {
        int gi = t0 - 4 + tid; if (gi < 0) gi = 0;
        sf[tid] = __ldg((const float4*)features + (size_t)b * S_LEN + gi);
    }

    u64 wp[17];
    float bias = 0.0f;
    if (tid < GATES) {
        const float* wr = w_ih0 + tid * 35;
#pragma unroll
        for (int j = 0; j < 17; j++) wp[j] = pack2(wr[2 * j], wr[2 * j + 1]);
        bias = b_ih0[tid] + b_hh0[tid];
    }
    __syncthreads();

    if (tid < 64) {
        const int t = t0 + tid;
        float a[5][5];
#pragma unroll
        for (int k = 0; k < 5; k++) {
            int gi = t + k - 4;
            int idx = gi < 0 ? 0 : gi;
            float4 fv = sf[tid + k];
            a[k][0] = (float)idx * (1.0f / 255.0f);
            a[k][1] = fv.x; a[k][2] = fv.y; a[k][3] = fv.z; a[k][4] = fv.w;
        }
        float* x = xs[tid];
        x[0] = a[4][1]; x[1] = a[4][2]; x[2] = a[4][3]; x[3] = a[4][4];
#pragma unroll
        for (int i = 0; i < 5; i++) x[4 + i] = a[4][i] - a[0][i];
#pragma unroll
        for (int i = 0; i < 5; i++) {
#pragma unroll
            for (int j = 0; j < 5; j++) {
                float s = 0.0f;
#pragma unroll
                for (int k = 0; k < 4; k++) s += (a[k + 1][i] - a[k][i]) * a[k][j];
                x[9 + i * 5 + j] = s;
            }
        }
        x[34] = 0.0f; x[35] = 0.0f;
    }
    __syncthreads();

    if (tid < GATES) {
        const size_t row0 = (size_t)b * S_LEN + t0;
        for (int r = 0; r < 64; r += 2) {
            const ulonglong2* xA = (const ulonglong2*)&xs[r][0];
            const ulonglong2* xB = (const ulonglong2*)&xs[r + 1][0];
            u64 aA = 0ull, aB = 0ull;
#pragma unroll
            for (int q = 0; q < 8; q++) {
                ulonglong2 vA = xA[q], vB = xB[q];
                aA = ffma2(wp[2 * q],     vA.x, aA);
                aB = ffma2(wp[2 * q],     vB.x, aB);
                aA = ffma2(wp[2 * q + 1], vA.y, aA);
                aB = ffma2(wp[2 * q + 1], vB.y, aB);
            }
            u64 tA = ((const u64*)&xs[r][0])[16];
            u64 tB = ((const u64*)&xs[r + 1][0])[16];
            aA = ffma2(wp[16], tA, aA);
            aB = ffma2(wp[16], tB, aB);
            float2 fA = unpack2(aA), fB = unpack2(aB);
            size_t ra = row0 + r, rb = row0 + r + 1;     // row = b*S + t
            size_t ia = ((ra & 255) * (size_t)B_TOT + (ra >> 8)) * 200 + tid;
            size_t ib = ((rb & 255) * (size_t)B_TOT + (rb >> 8)) * 200 + tid;
            g_pre0[ia] = fA.x + fA.y + bias;
            g_pre0[ib] = fB.x + fB.y + bias;
        }
    }
}

// ---------------------------------------------------------------------------
// K2: recurrent kernel. One CTA = BT batches, 256 steps, 256 threads.
// Z0 weights (W_hh0) live in SMEM transposed (lane-major, conflict-free);
// Z1 weights (W_ih1/W_hh1) stay register-resident (104 regs). This keeps
// total register demand ~170 -> no spills (R6 hit the 255 cap and spilled).
// ---------------------------------------------------------------------------
// dynamic SMEM layout (floats):
//   P0    @ 0      : 5600  (BT*200)
//   P1    @ 5600   : 5600
//   h0s   @ 11200  : 1456  (BT*52)
//   h1s   @ 12656  : 1456
//   w1s   @ 14112  : 1300  (25*52)
//   w0T   @ 15412  : 10400 (13 x 200 ulonglong2: W_hh0 transposed, padded)
//   pd_s  @ 25812  : 28
//   b1s   @ 25840  : 25
//   w2s   @ 25865  : 25
//   b2s   @ 25890  : 1
#define SM_FLOATS 25891

__global__ __launch_bounds__(NT, 1) void rec_kernel(
    const float* __restrict__ w_ih0, const float* __restrict__ w_hh0,
    const float* __restrict__ w_ih1, const float* __restrict__ w_hh1,
    const float* __restrict__ b_ih1, const float* __restrict__ b_hh1,
    const float* __restrict__ w1,    const float* __restrict__ b1,
    const float* __restrict__ w2,    const float* __restrict__ b2,
    float* __restrict__ out)
{
    extern __shared__ __align__(16) float sm[];
    float* h0s  = sm + 11200;
    float* h1s  = sm + 12656;
    float* w1s  = sm + 14112;
    ulonglong2* w0T = (ulonglong2*)(sm + 15412);   // [jj][o], jj<13, o<200
    float* pd_s = sm + 25812;
    float* b1s  = sm + 25840;
    float* w2s  = sm + 25865;
    float* b2sp = sm + 25890;

    const int tid = threadIdx.x;
    const int wid = tid >> 5;
    const int lane = tid & 31;
    const int b0  = blockIdx.x * BT;
    int bt = B_TOT - b0; if (bt > BT) bt = BT;     // 28 or 8 (mult of 4)

    // --- Z1 weights register-resident (26+26 u64 = 104 regs) ---
    u64 wi1p[26], wh1p[26];
    float wpd = 0.0f, bias1 = 0.0f;
    if (tid < GATES) {
        const float* r1 = w_ih1 + tid * 50;
        const float* r2 = w_hh1 + tid * 50;
#pragma unroll
        for (int q = 0; q < 25; q++) {
            wi1p[q] = pack2(r1[2 * q], r1[2 * q + 1]);
            wh1p[q] = pack2(r2[2 * q], r2[2 * q + 1]);
        }
        wi1p[25] = 0ull; wh1p[25] = 0ull;
        wpd   = w_ih0[tid * 35 + 34];
        bias1 = b_ih1[tid] + b_hh1[tid];
    }

    // --- Z0 weights -> SMEM transposed: w0T[jj][o] = (w[4jj..4jj+1], w[4jj+2..4jj+3]) ---
    for (int i = tid; i < 13 * 200; i += NT) {
        int jj = i / 200, o = i - jj * 200;
        const float* wr = w_hh0 + o * 50 + 4 * jj;
        float e0 = wr[0], e1 = wr[1];
        float e2 = (4 * jj + 2 < 50) ? wr[2] : 0.0f;
        float e3 = (4 * jj + 3 < 50) ? wr[3] : 0.0f;
        ulonglong2 v; v.x = pack2(e0, e1); v.y = pack2(e2, e3);
        w0T[i] = v;
    }

    // --- init state / head weights ---
    for (int i = tid; i < BT * 52; i += NT) { h0s[i] = 0.0f; h1s[i] = 0.0f; }
    for (int i = tid; i < 1300; i += NT) {
        int j = i / 52, k = i - j * 52;
        w1s[i] = (k < 50) ? w1[j * 50 + k] : 0.0f;
    }
    if (tid < 25) { b1s[tid] = b1[tid]; w2s[tid] = w2[tid]; }
    if (tid < BT) pd_s[tid] = 0.0f;
    if (tid == 0) b2sp[0] = b2[0];
    float c0r[6], c1r[6];
#pragma unroll
    for (int n = 0; n < 6; n++) { c0r[n] = 0.0f; c1r[n] = 0.0f; }

    const int nact = bt * 50;
    const int nz4  = bt * 50;    // float4 count of one pre0 tile
    const uint32_t sm0 = (uint32_t)__cvta_generic_to_shared(sm);
    const uint32_t sm1 = (uint32_t)__cvta_generic_to_shared(sm + 5600);

    // prologue: fill P0 with pre0(t=0)
    {
        const float4* psrc = (const float4*)(g_pre0 + (size_t)b0 * 200);
        for (int idx = tid; idx < nz4; idx += NT)
            cpasync16(sm0 + idx * 16, psrc + idx);
        cpcommit(); cpwait0();
    }
    __syncthreads();

    for (int t = 0; t < S_LEN; t++) {
        float* cur = (t & 1) ? (sm + 5600) : sm;
        const uint32_t nxtsm = (t & 1) ? sm0 : sm1;

        // --- Z0 (threads<200, W_hh0 from SMEM)  ||  warp 7 prefetches t+1 ---
        if (tid < GATES) {
            const int o = tid;
            for (int b = 0; b < bt; b += 4) {
                const ulonglong2* hA = (const ulonglong2*)(h0s + (b + 0) * 52);
                const ulonglong2* hB = (const ulonglong2*)(h0s + (b + 1) * 52);
                const ulonglong2* hC = (const ulonglong2*)(h0s + (b + 2) * 52);
                const ulonglong2* hD = (const ulonglong2*)(h0s + (b + 3) * 52);
                u64 aA = 0ull, aB = 0ull, aC = 0ull, aD = 0ull;
#pragma unroll
                for (int jj = 0; jj < 13; jj++) {
                    ulonglong2 w = w0T[jj * 200 + o];
                    ulonglong2 vA = hA[jj], vB = hB[jj], vC = hC[jj], vD = hD[jj];
                    aA = ffma2(w.x, vA.x, aA); aA = ffma2(w.y, vA.y, aA);
                    aB = ffma2(w.x, vB.x, aB); aB = ffma2(w.y, vB.y, aB);
                    aC = ffma2(w.x, vC.x, aC); aC = ffma2(w.y, vC.y, aC);
                    aD = ffma2(w.x, vD.x, aD); aD = ffma2(w.y, vD.y, aD);
                }
                float2 fA = unpack2(aA), fB = unpack2(aB), fC = unpack2(aC), fD = unpack2(aD);
                cur[(b + 0) * 200 + o] += fA.x + fA.y + wpd * pd_s[b + 0];
                cur[(b + 1) * 200 + o] += fB.x + fB.y + wpd * pd_s[b + 1];
                cur[(b + 2) * 200 + o] += fC.x + fC.y + wpd * pd_s[b + 2];
                cur[(b + 3) * 200 + o] += fD.x + fD.y + wpd * pd_s[b + 3];
            }
        } else if (wid == 7 && t + 1 < S_LEN) {
            const float4* psrc = (const float4*)(g_pre0 + ((size_t)(t + 1) * B_TOT + b0) * 200);
            for (int idx = lane; idx < nz4; idx += 32)
                cpasync16(nxtsm + idx * 16, psrc + idx);
            cpcommit();
        }
        __syncthreads();

        // --- act0 ---
#pragma unroll
        for (int n = 0; n < 6; n++) {
            int idx = tid + n * NT;
            if (idx < nact) {
                int b = idx / 50, u = idx - b * 50;
                const float* zr = cur + b * 200;
                float iv = zr[u], fv = zr[u + 50], gv = zr[u + 100], ov = zr[u + 150];
                float c = sigf(fv) * c0r[n] + sigf(iv) * tanha(gv);
                c0r[n] = c;
                h0s[b * 52 + u] = sigf(ov) * tanha(c);
            }
        }
        __syncthreads();

        // --- Z1 (register weights, 2-way batch unroll, fine interleave) ---
        if (tid < GATES) {
            const int o = tid;
            for (int b = 0; b < bt; b += 2) {
                const ulonglong2* gA = (const ulonglong2*)(h0s + (b + 0) * 52);
                const ulonglong2* gB = (const ulonglong2*)(h0s + (b + 1) * 52);
                const ulonglong2* kA = (const ulonglong2*)(h1s + (b + 0) * 52);
                const ulonglong2* kB = (const ulonglong2*)(h1s + (b + 1) * 52);
                u64 aA = 0ull, aB = 0ull;
#pragma unroll
                for (int j = 0; j < 13; j++) {
                    ulonglong2 vA = gA[j], vB = gB[j];
                    aA = ffma2(wi1p[2 * j],     vA.x, aA);
                    aB = ffma2(wi1p[2 * j],     vB.x, aB);
                    aA = ffma2(wi1p[2 * j + 1], vA.y, aA);
                    aB = ffma2(wi1p[2 * j + 1], vB.y, aB);
                    ulonglong2 uA = kA[j], uB = kB[j];
                    aA = ffma2(wh1p[2 * j],     uA.x, aA);
                    aB = ffma2(wh1p[2 * j],     uB.x, aB);
                    aA = ffma2(wh1p[2 * j + 1], uA.y, aA);
                    aB = ffma2(wh1p[2 * j + 1], uB.y, aB);
                }
                float2 fA = unpack2(aA), fB = unpack2(aB);
                cur[(b + 0) * 200 + o] = bias1 + fA.x + fA.y;
                cur[(b + 1) * 200 + o] = bias1 + fB.x + fB.y;
            }
        }
        __syncthreads();

        // --- act1 ---
#pragma unroll
        for (int n = 0; n < 6; n++) {
            int idx = tid + n * NT;
            if (idx < nact) {
                int b = idx / 50, u = idx - b * 50;
                const float* zr = cur + b * 200;
                float iv = zr[u], fv = zr[u + 50], gv = zr[u + 100], ov = zr[u + 150];
                float c = sigf(fv) * c1r[n] + sigf(iv) * tanha(gv);
                c1r[n] = c;
                h1s[b * 52 + u] = sigf(ov) * tanha(c);
            }
        }
        __syncthreads();

        // --- head: warp-per-batch, lanes 0-24 = hidden units, shfl reduce ---
        for (int b = wid; b < bt; b += 8) {
            float v = 0.0f;
            if (lane < 25) {
                const u64* wv = (const u64*)(w1s + lane * 52);
                const u64* hv = (const u64*)(h1s + b * 52);
                u64 acc = 0ull;
#pragma unroll
                for (int q = 0; q < 26; q++) acc = ffma2(wv[q], hv[q], acc);
                float2 f = unpack2(acc);
                v = w2s[lane] * fmaxf(f.x + f.y + b1s[lane], 0.0f);
            }
#pragma unroll
            for (int k = 16; k > 0; k >>= 1) v += __shfl_xor_sync(0xFFFFFFFFu, v, k);
            if (lane == 0) {
                float nd = pd_s[b] + 0.2f * tanha(v + b2sp[0]);
                nd = fminf(fmaxf(nd, -1.5f), 1.5f);
                pd_s[b] = nd;
                out[(size_t)(b0 + b) * S_LEN + t] = nd;
            }
        }
        if (wid == 7) cpwait0();   // prefetch must land before next step
        __syncthreads();
    }
}

// ---------------------------------------------------------------------------
extern "C" void kernel_launch(void* const* d_in, const int* in_sizes, int n_in,
                              void* d_out, int out_size) {
    const float* features = (const float*)d_in[0];
    const float* w_ih0    = (const float*)d_in[1];
    const float* w_hh0    = (const float*)d_in[2];
    const float* b_ih0    = (const float*)d_in[3];
    const float* b_hh0    = (const float*)d_in[4];
    const float* w_ih1    = (const float*)d_in[5];
    const float* w_hh1    = (const float*)d_in[6];
    const float* b_ih1    = (const float*)d_in[7];
    const float* b_hh1    = (const float*)d_in[8];
    const float* w1       = (const float*)d_in[9];
    const float* b1       = (const float*)d_in[10];
    const float* w2       = (const float*)d_in[11];
    const float* b2       = (const float*)d_in[12];
    float* out = (float*)d_out;

    static bool attr_set = false;
    if (!attr_set) {
        cudaFuncSetAttribute(rec_kernel, cudaFuncAttributeMaxDynamicSharedMemorySize,
                             SM_FLOATS * 4);
        attr_set = true;
    }

    pre0f_kernel<<<(B_TOT * S_LEN) / 64, 256>>>(features, w_ih0, b_ih0, b_hh0);
    rec_kernel<<<(B_TOT + BT - 1) / BT, NT, SM_FLOATS * 4>>>(
        w_ih0, w_hh0, w_ih1, w_hh1, b_ih1, b_hh1, w1, b1, w2, b2, out);
}

// round 8
// speedup vs baseline: 1.1962x; 1.1962x over previous
#include <cuda_runtime.h>
#include <cstdint>

// ---------------------------------------------------------------------------
// HybridSigLSTM: rolling signature + 2-layer LSTM(H=50) + MLP head + pd clip
// B=4096, S=256, DIN=4, WIN=5, D_AUG=5, SIG=30, COMB=35, GATES=4*50=200
// ---------------------------------------------------------------------------

#define B_TOT 4096
#define S_LEN 256
#define GATES 200
#define BT    28      // batch elements per CTA in recurrent kernel
#define NT    768     // threads in recurrent kernel (3 weight groups)

typedef unsigned long long u64;

// scratch (device global: allocation-free rule)
__device__ float g_pre0[(size_t)B_TOT * S_LEN * 200];  // [t][b][o]

// ---------------- helpers ----------------
__device__ __forceinline__ u64 ffma2(u64 a, u64 b, u64 c) {
    u64 d;
    asm("fma.rn.f32x2 %0, %1, %2, %3;" : "=l"(d) : "l"(a), "l"(b), "l"(c));
    return d;
}
__device__ __forceinline__ u64 pack2(float a, float b) {
    u64 r;
    asm("mov.b64 %0, {%1, %2};" : "=l"(r) : "f"(a), "f"(b));
    return r;
}
__device__ __forceinline__ float2 unpack2(u64 v) {
    float2 f;
    asm("mov.b64 {%0, %1}, %2;" : "=f"(f.x), "=f"(f.y) : "l"(v));
    return f;
}
__device__ __forceinline__ float ex2f(float x) {
    float y; asm("ex2.approx.f32 %0, %1;" : "=f"(y) : "f"(x)); return y;
}
__device__ __forceinline__ float rcpf(float x) {
    float y; asm("rcp.approx.f32 %0, %1;" : "=f"(y) : "f"(x)); return y;
}
__device__ __forceinline__ float sigf(float x) {
    return rcpf(1.0f + ex2f(-1.4426950408889634f * x));
}
__device__ __forceinline__ float tanha(float x) {
    return 2.0f * rcpf(1.0f + ex2f(-2.8853900817779268f * x)) - 1.0f;
}
__device__ __forceinline__ void cpasync16(uint32_t saddr, const void* gptr) {
    asm volatile("cp.async.cg.shared.global [%0], [%1], 16;" :: "r"(saddr), "l"(gptr));
}
__device__ __forceinline__ void cpcommit() {
    asm volatile("cp.async.commit_group;" ::: "memory");
}
__device__ __forceinline__ void cpwait0() {
    asm volatile("cp.async.wait_group 0;" ::: "memory");
}

// ---------------------------------------------------------------------------
// K1: fused signature + input projection. One CTA = full sequence of one b.
// ---------------------------------------------------------------------------
__global__ __launch_bounds__(256) void pre0f_kernel(const float* __restrict__ features,
                                                    const float* __restrict__ w_ih0,
                                                    const float* __restrict__ b_ih0,
                                                    const float* __restrict__ b_hh0) {
    __shared__ __align__(16) float4 sf[260];         // raw feature window (t-4..t+255)
    __shared__ __align__(16) float xs[256][36];
    const int tid = threadIdx.x;
    const int b   = blockIdx.x;

    for (int i = tid; i < 260; i += 256) {
        int gi = i - 4; if (gi < 0) gi = 0;
        sf[i] = __ldg((const float4*)features + (size_t)b * S_LEN + gi);
    }

    u64 wp[17];
    float bias = 0.0f;
    if (tid < GATES) {
        const float* wr = w_ih0 + tid * 35;
#pragma unroll
        for (int j = 0; j < 17; j++) wp[j] = pack2(wr[2 * j], wr[2 * j + 1]);
        bias = b_ih0[tid] + b_hh0[tid];
    }
    __syncthreads();

    {   // every thread computes sig features for row t = tid
        const int t = tid;
        float a[5][5];
#pragma unroll
        for (int k = 0; k < 5; k++) {
            int gi = t + k - 4;
            int idx = gi < 0 ? 0 : gi;
            float4 fv = sf[t + k];
            a[k][0] = (float)idx * (1.0f / 255.0f);
            a[k][1] = fv.x; a[k][2] = fv.y; a[k][3] = fv.z; a[k][4] = fv.w;
        }
        float* x = xs[t];
        x[0] = a[4][1]; x[1] = a[4][2]; x[2] = a[4][3]; x[3] = a[4][4];
#pragma unroll
        for (int i = 0; i < 5; i++) x[4 + i] = a[4][i] - a[0][i];
#pragma unroll
        for (int i = 0; i < 5; i++) {
#pragma unroll
            for (int j = 0; j < 5; j++) {
                float s = 0.0f;
#pragma unroll
                for (int k = 0; k < 4; k++) s += (a[k + 1][i] - a[k][i]) * a[k][j];
                x[9 + i * 5 + j] = s;
            }
        }
        x[34] = 0.0f; x[35] = 0.0f;
    }
    __syncthreads();

    if (tid < GATES) {
        for (int r = 0; r < 256; r += 2) {
            const ulonglong2* xA = (const ulonglong2*)&xs[r][0];
            const ulonglong2* xB = (const ulonglong2*)&xs[r + 1][0];
            u64 aA = 0ull, aB = 0ull;
#pragma unroll
            for (int q = 0; q < 8; q++) {
                ulonglong2 vA = xA[q], vB = xB[q];
                aA = ffma2(wp[2 * q],     vA.x, aA);
                aB = ffma2(wp[2 * q],     vB.x, aB);
                aA = ffma2(wp[2 * q + 1], vA.y, aA);
                aB = ffma2(wp[2 * q + 1], vB.y, aB);
            }
            u64 tA = ((const u64*)&xs[r][0])[16];
            u64 tB = ((const u64*)&xs[r + 1][0])[16];
            aA = ffma2(wp[16], tA, aA);
            aB = ffma2(wp[16], tB, aB);
            float2 fA = unpack2(aA), fB = unpack2(aB);
            size_t ia = ((size_t)r       * B_TOT + b) * 200 + tid;   // [t][b][o]
            size_t ib = ((size_t)(r + 1) * B_TOT + b) * 200 + tid;
            g_pre0[ia] = fA.x + fA.y + bias;
            g_pre0[ib] = fB.x + fB.y + bias;
        }
    }
}

// ---------------------------------------------------------------------------
// K2: warp-specialized recurrent kernel. 768 threads, 24 warps, 1 CTA/SM.
//   A (tid<200):        W_hh0 row in regs -> Z0
//   B (warps 8-15):     W_ih1 row in regs (tid 256-455) -> z1 in ph3;
//                       in ph1: deferred head(t-1) + cp.async prefetch
//   C (tid 512-711):    W_hh1 row in regs -> p2 = Whh1*h1(t-1), parallel w/ Z0
// pd term moved into act0 (wpd_s in SMEM) so head can lag one step.
// ---------------------------------------------------------------------------
// dynamic SMEM layout (floats):
//   P0 @0 (5600) | P1 @5600 | p2s @11200 | h0s @16800 (1456) | h1s @18256
//   w1T @19712 (676 u64 = 1352) | pd_s @21064 (28) | wpd_s @21092 (200)
//   b1s @21292 (25) | w2s @21317 (25) | b2 @21342
#define SM_FLOATS 21344

__global__ __launch_bounds__(NT, 1) void rec_kernel(
    const float* __restrict__ w_ih0, const float* __restrict__ w_hh0,
    const float* __restrict__ w_ih1, const float* __restrict__ w_hh1,
    const float* __restrict__ b_ih1, const float* __restrict__ b_hh1,
    const float* __restrict__ w1,    const float* __restrict__ b1,
    const float* __restrict__ w2,    const float* __restrict__ b2,
    float* __restrict__ out)
{
    extern __shared__ __align__(16) float sm[];
    float* P0   = sm;
    float* P1   = sm + 5600;
    float* p2s  = sm + 11200;
    float* h0s  = sm + 16800;
    float* h1s  = sm + 18256;
    u64*   w1T  = (u64*)(sm + 19712);
    float* pd_s = sm + 21064;
    float* wpd_s= sm + 21092;
    float* b1s  = sm + 21292;
    float* w2s  = sm + 21317;
    float* b2sp = sm + 21342;

    const int tid  = threadIdx.x;
    const int wid  = tid >> 5;
    const int lane = tid & 31;
    const int b0   = blockIdx.x * BT;
    int bt = B_TOT - b0; if (bt > BT) bt = BT;     // 28 or 8 (even)

    // role: 0=A(Z0 / W_hh0), 1=B(z1 / W_ih1), 2=C(p2 / W_hh1), 3=helper
    int role = 3, o = 0;
    if (tid < 200)                    { role = 0; o = tid; }
    else if (tid >= 256 && tid < 456) { role = 1; o = tid - 256; }
    else if (tid >= 512 && tid < 712) { role = 2; o = tid - 512; }

    u64 wreg[26];
    float bias1 = 0.0f;
    if (role == 0) {
        const float* r = w_hh0 + o * 50;
#pragma unroll
        for (int q = 0; q < 25; q++) wreg[q] = pack2(r[2 * q], r[2 * q + 1]);
        wreg[25] = 0ull;
        wpd_s[o] = w_ih0[o * 35 + 34];
    } else if (role == 1) {
        const float* r = w_ih1 + o * 50;
#pragma unroll
        for (int q = 0; q < 25; q++) wreg[q] = pack2(r[2 * q], r[2 * q + 1]);
        wreg[25] = 0ull;
        bias1 = b_ih1[o] + b_hh1[o];
    } else if (role == 2) {
        const float* r = w_hh1 + o * 50;
#pragma unroll
        for (int q = 0; q < 25; q++) wreg[q] = pack2(r[2 * q], r[2 * q + 1]);
        wreg[25] = 0ull;
    }

    for (int i = tid; i < BT * 52; i += NT) { h0s[i] = 0.0f; h1s[i] = 0.0f; }
    for (int i = tid; i < 676; i += NT) {
        int uu = i / 26, j = i - uu * 26;
        w1T[i] = (j < 25 && uu < 25) ? pack2(w1[j * 50 + 2 * uu], w1[j * 50 + 2 * uu + 1]) : 0ull;
    }
    if (tid < 25) { b1s[tid] = b1[tid]; w2s[tid] = w2[tid]; }
    if (tid < BT) pd_s[tid] = 0.0f;
    if (tid == 0) b2sp[0] = b2[0];
    float c0r[2], c1r[2];
    c0r[0] = c0r[1] = c1r[0] = c1r[1] = 0.0f;

    const int nact = bt * 50;
    const int nz4  = bt * 50;   // float4 count of a pre0 tile
    const uint32_t smP0 = (uint32_t)__cvta_generic_to_shared(P0);
    const uint32_t smP1 = (uint32_t)__cvta_generic_to_shared(P1);

    // prologue: fetch pre0(t=0) into P0
    {
        const float4* psrc = (const float4*)(g_pre0 + (size_t)b0 * 200);
        for (int idx = tid; idx < nz4; idx += NT)
            cpasync16(smP0 + idx * 16, psrc + idx);
        cpcommit(); cpwait0();
    }
    __syncthreads();

    for (int t = 0; t < S_LEN; t++) {
        float* cur = (t & 1) ? P1 : P0;
        const uint32_t nxt = (t & 1) ? smP0 : smP1;

        // ---- ph1: A: Z0 | C: p2 | B-warps: head(t-1) + prefetch(t+1) ----
        if (role == 0) {
            for (int b = 0; b < bt; b += 2) {
                const ulonglong2* hA = (const ulonglong2*)(h0s + b * 52);
                const ulonglong2* hB = (const ulonglong2*)(h0s + (b + 1) * 52);
                u64 aA = 0ull, aB = 0ull;
#pragma unroll
                for (int j = 0; j < 13; j++) {
                    ulonglong2 vA = hA[j], vB = hB[j];
                    aA = ffma2(wreg[2 * j],     vA.x, aA);
                    aB = ffma2(wreg[2 * j],     vB.x, aB);
                    aA = ffma2(wreg[2 * j + 1], vA.y, aA);
                    aB = ffma2(wreg[2 * j + 1], vB.y, aB);
                }
                float2 fA = unpack2(aA), fB = unpack2(aB);
                cur[b * 200 + o]       += fA.x + fA.y;
                cur[(b + 1) * 200 + o] += fB.x + fB.y;
            }
        } else if (role == 2) {
            for (int b = 0; b < bt; b += 2) {
                const ulonglong2* hA = (const ulonglong2*)(h1s + b * 52);
                const ulonglong2* hB = (const ulonglong2*)(h1s + (b + 1) * 52);
                u64 aA = 0ull, aB = 0ull;
#pragma unroll
                for (int j = 0; j < 13; j++) {
                    ulonglong2 vA = hA[j], vB = hB[j];
                    aA = ffma2(wreg[2 * j],     vA.x, aA);
                    aB = ffma2(wreg[2 * j],     vB.x, aB);
                    aA = ffma2(wreg[2 * j + 1], vA.y, aA);
                    aB = ffma2(wreg[2 * j + 1], vB.y, aB);
                }
                float2 fA = unpack2(aA), fB = unpack2(aB);
                p2s[b * 200 + o]       = fA.x + fA.y;
                p2s[(b + 1) * 200 + o] = fB.x + fB.y;
            }
        } else if (wid >= 8 && wid < 16) {
            if (t > 0) {
                for (int b = wid - 8; b < bt; b += 8) {
                    float v = 0.0f;
                    if (lane < 25) {
                        const u64* hv = (const u64*)(h1s + b * 52);
                        u64 acc = 0ull;
#pragma unroll
                        for (int uu = 0; uu < 25; uu++)
                            acc = ffma2(w1T[uu * 26 + lane], hv[uu], acc);
                        float2 f = unpack2(acc);
                        v = w2s[lane] * fmaxf(f.x + f.y + b1s[lane], 0.0f);
                    }
#pragma unroll
                    for (int k = 16; k > 0; k >>= 1) v += __shfl_xor_sync(0xFFFFFFFFu, v, k);
                    if (lane == 0) {
                        float nd = pd_s[b] + 0.2f * tanha(v + b2sp[0]);
                        nd = fminf(fmaxf(nd, -1.5f), 1.5f);
                        pd_s[b] = nd;
                        out[(size_t)(b0 + b) * S_LEN + (t - 1)] = nd;
                    }
                }
            }
            if (t + 1 < S_LEN) {
                const float4* psrc = (const float4*)(g_pre0 + ((size_t)(t + 1) * B_TOT + b0) * 200);
                for (int idx = tid - 256; idx < nz4; idx += 256)
                    cpasync16(nxt + idx * 16, psrc + idx);
            }
            cpcommit();
        }
        __syncthreads();

        // ---- act0: adds wpd*pd(t-1) term here ----
#pragma unroll
        for (int n = 0; n < 2; n++) {
            int idx = tid + n * NT;
            if (idx < nact) {
                int b = idx / 50, u = idx - b * 50;
                const float* zr = cur + b * 200;
                float pdb = pd_s[b];
                float iv = zr[u]       + wpd_s[u]       * pdb;
                float fv = zr[u + 50]  + wpd_s[u + 50]  * pdb;
                float gv = zr[u + 100] + wpd_s[u + 100] * pdb;
                float ov = zr[u + 150] + wpd_s[u + 150] * pdb;
                float c = sigf(fv) * c0r[n] + sigf(iv) * tanha(gv);
                c0r[n] = c;
                h0s[b * 52 + u] = sigf(ov) * tanha(c);
            }
        }
        __syncthreads();

        // ---- ph3: B: z1 = bias1 + Wih1*h0new + p2 ----
        if (role == 1) {
            for (int b = 0; b < bt; b += 2) {
                const ulonglong2* hA = (const ulonglong2*)(h0s + b * 52);
                const ulonglong2* hB = (const ulonglong2*)(h0s + (b + 1) * 52);
                u64 aA = 0ull, aB = 0ull;
#pragma unroll
                for (int j = 0; j < 13; j++) {
                    ulonglong2 vA = hA[j], vB = hB[j];
                    aA = ffma2(wreg[2 * j],     vA.x, aA);
                    aB = ffma2(wreg[2 * j],     vB.x, aB);
                    aA = ffma2(wreg[2 * j + 1], vA.y, aA);
                    aB = ffma2(wreg[2 * j + 1], vB.y, aB);
                }
                float2 fA = unpack2(aA), fB = unpack2(aB);
                cur[b * 200 + o]       = bias1 + fA.x + fA.y + p2s[b * 200 + o];
                cur[(b + 1) * 200 + o] = bias1 + fB.x + fB.y + p2s[(b + 1) * 200 + o];
            }
        }
        __syncthreads();

        // ---- act1 ----
#pragma unroll
        for (int n = 0; n < 2; n++) {
            int idx = tid + n * NT;
            if (idx < nact) {
                int b = idx / 50, u = idx - b * 50;
                const float* zr = cur + b * 200;
                float iv = zr[u], fv = zr[u + 50], gv = zr[u + 100], ov = zr[u + 150];
                float c = sigf(fv) * c1r[n] + sigf(iv) * tanha(gv);
                c1r[n] = c;
                h1s[b * 52 + u] = sigf(ov) * tanha(c);
            }
        }
        cpwait0();          // prefetch must land before ph1(t+1) reads it
        __syncthreads();
    }

    // ---- epilogue: head for t = S_LEN-1 ----
    if (wid >= 8 && wid < 16) {
        for (int b = wid - 8; b < bt; b += 8) {
            float v = 0.0f;
            if (lane < 25) {
                const u64* hv = (const u64*)(h1s + b * 52);
                u64 acc = 0ull;
#pragma unroll
                for (int uu = 0; uu < 25; uu++)
                    acc = ffma2(w1T[uu * 26 + lane], hv[uu], acc);
                float2 f = unpack2(acc);
                v = w2s[lane] * fmaxf(f.x + f.y + b1s[lane], 0.0f);
            }
#pragma unroll
            for (int k = 16; k > 0; k >>= 1) v += __shfl_xor_sync(0xFFFFFFFFu, v, k);
            if (lane == 0) {
                float nd = pd_s[b] + 0.2f * tanha(v + b2sp[0]);
                nd = fminf(fmaxf(nd, -1.5f), 1.5f);
                out[(size_t)(b0 + b) * S_LEN + (S_LEN - 1)] = nd;
            }
        }
    }
}

// ---------------------------------------------------------------------------
extern "C" void kernel_launch(void* const* d_in, const int* in_sizes, int n_in,
                              void* d_out, int out_size) {
    const float* features = (const float*)d_in[0];
    const float* w_ih0    = (const float*)d_in[1];
    const float* w_hh0    = (const float*)d_in[2];
    const float* b_ih0    = (const float*)d_in[3];
    const float* b_hh0    = (const float*)d_in[4];
    const float* w_ih1    = (const float*)d_in[5];
    const float* w_hh1    = (const float*)d_in[6];
    const float* b_ih1    = (const float*)d_in[7];
    const float* b_hh1    = (const float*)d_in[8];
    const float* w1       = (const float*)d_in[9];
    const float* b1       = (const float*)d_in[10];
    const float* w2       = (const float*)d_in[11];
    const float* b2       = (const float*)d_in[12];
    float* out = (float*)d_out;

    static bool attr_set = false;
    if (!attr_set) {
        cudaFuncSetAttribute(rec_kernel, cudaFuncAttributeMaxDynamicSharedMemorySize,
                             SM_FLOATS * 4);
        attr_set = true;
    }

    pre0f_kernel<<<B_TOT, 256>>>(features, w_ih0, b_ih0, b_hh0);
    rec_kernel<<<(B_TOT + BT - 1) / BT, NT, SM_FLOATS * 4>>>(
        w_ih0, w_hh0, w_ih1, w_hh1, b_ih1, b_hh1, w1, b1, w2, b2, out);
}

// round 10
// speedup vs baseline: 1.3206x; 1.1040x over previous
#include <cuda_runtime.h>
#include <cstdint>

// ---------------------------------------------------------------------------
// HybridSigLSTM: rolling signature + 2-layer LSTM(H=50) + MLP head + pd clip
// B=4096, S=256, DIN=4, WIN=5, D_AUG=5, SIG=30, COMB=35, GATES=4*50=200
// ---------------------------------------------------------------------------

#define B_TOT 4096
#define S_LEN 256
#define GATES 200
#define BT    28      // batch elements per CTA in recurrent kernel
#define NT    384     // threads in recurrent kernel (12 warps)

typedef unsigned long long u64;

// scratch (device global: allocation-free rule)
__device__ float g_pre0[(size_t)B_TOT * S_LEN * 200];  // [t][b][o]

// ---------------- helpers ----------------
__device__ __forceinline__ u64 ffma2(u64 a, u64 b, u64 c) {
    u64 d;
    asm("fma.rn.f32x2 %0, %1, %2, %3;" : "=l"(d) : "l"(a), "l"(b), "l"(c));
    return d;
}
__device__ __forceinline__ u64 pack2(float a, float b) {
    u64 r;
    asm("mov.b64 %0, {%1, %2};" : "=l"(r) : "f"(a), "f"(b));
    return r;
}
__device__ __forceinline__ float2 unpack2(u64 v) {
    float2 f;
    asm("mov.b64 {%0, %1}, %2;" : "=f"(f.x), "=f"(f.y) : "l"(v));
    return f;
}
__device__ __forceinline__ float ex2f(float x) {
    float y; asm("ex2.approx.f32 %0, %1;" : "=f"(y) : "f"(x)); return y;
}
__device__ __forceinline__ float rcpf(float x) {
    float y; asm("rcp.approx.f32 %0, %1;" : "=f"(y) : "f"(x)); return y;
}
__device__ __forceinline__ float sigf(float x) {
    return rcpf(1.0f + ex2f(-1.4426950408889634f * x));
}
__device__ __forceinline__ float tanha(float x) {
    return 2.0f * rcpf(1.0f + ex2f(-2.8853900817779268f * x)) - 1.0f;
}
__device__ __forceinline__ void cpasync16(uint32_t saddr, const void* gptr) {
    asm volatile("cp.async.cg.shared.global [%0], [%1], 16;" :: "r"(saddr), "l"(gptr));
}
__device__ __forceinline__ void cpcommit() {
    asm volatile("cp.async.commit_group;" ::: "memory");
}
__device__ __forceinline__ void cpwait0() {
    asm volatile("cp.async.wait_group 0;" ::: "memory");
}

// ---------------------------------------------------------------------------
// K1: fused signature + input projection. One CTA = full sequence of one b.
// ---------------------------------------------------------------------------
__global__ __launch_bounds__(256) void pre0f_kernel(const float* __restrict__ features,
                                                    const float* __restrict__ w_ih0,
                                                    const float* __restrict__ b_ih0,
                                                    const float* __restrict__ b_hh0) {
    __shared__ __align__(16) float4 sf[260];         // raw feature window (t-4..t+255)
    __shared__ __align__(16) float xs[256][36];
    const int tid = threadIdx.x;
    const int b   = blockIdx.x;

    for (int i = tid; i < 260; i += 256) {
        int gi = i - 4; if (gi < 0) gi = 0;
        sf[i] = __ldg((const float4*)features + (size_t)b * S_LEN + gi);
    }

    u64 wp[17];
    float bias = 0.0f;
    if (tid < GATES) {
        const float* wr = w_ih0 + tid * 35;
#pragma unroll
        for (int j = 0; j < 17; j++) wp[j] = pack2(wr[2 * j], wr[2 * j + 1]);
        bias = b_ih0[tid] + b_hh0[tid];
    }
    __syncthreads();

    {   // every thread computes sig features for row t = tid
        const int t = tid;
        float a[5][5];
#pragma unroll
        for (int k = 0; k < 5; k++) {
            int gi = t + k - 4;
            int idx = gi < 0 ? 0 : gi;
            float4 fv = sf[t + k];
            a[k][0] = (float)idx * (1.0f / 255.0f);
            a[k][1] = fv.x; a[k][2] = fv.y; a[k][3] = fv.z; a[k][4] = fv.w;
        }
        float* x = xs[t];
        x[0] = a[4][1]; x[1] = a[4][2]; x[2] = a[4][3]; x[3] = a[4][4];
#pragma unroll
        for (int i = 0; i < 5; i++) x[4 + i] = a[4][i] - a[0][i];
#pragma unroll
        for (int i = 0; i < 5; i++) {
#pragma unroll
            for (int j = 0; j < 5; j++) {
                float s = 0.0f;
#pragma unroll
                for (int k = 0; k < 4; k++) s += (a[k + 1][i] - a[k][i]) * a[k][j];
                x[9 + i * 5 + j] = s;
            }
        }
        x[34] = 0.0f; x[35] = 0.0f;
    }
    __syncthreads();

    if (tid < GATES) {
        for (int r = 0; r < 256; r += 2) {
            const ulonglong2* xA = (const ulonglong2*)&xs[r][0];
            const ulonglong2* xB = (const ulonglong2*)&xs[r + 1][0];
            u64 aA = 0ull, aB = 0ull;
#pragma unroll
            for (int q = 0; q < 8; q++) {
                ulonglong2 vA = xA[q], vB = xB[q];
                aA = ffma2(wp[2 * q],     vA.x, aA);
                aB = ffma2(wp[2 * q],     vB.x, aB);
                aA = ffma2(wp[2 * q + 1], vA.y, aA);
                aB = ffma2(wp[2 * q + 1], vB.y, aB);
            }
            u64 tA = ((const u64*)&xs[r][0])[16];
            u64 tB = ((const u64*)&xs[r + 1][0])[16];
            aA = ffma2(wp[16], tA, aA);
            aB = ffma2(wp[16], tB, aB);
            float2 fA = unpack2(aA), fB = unpack2(aB);
            size_t ia = ((size_t)r       * B_TOT + b) * 200 + tid;   // [t][b][o]
            size_t ib = ((size_t)(r + 1) * B_TOT + b) * 200 + tid;
            g_pre0[ia] = fA.x + fA.y + bias;
            g_pre0[ib] = fB.x + fB.y + bias;
        }
    }
}

// ---------------------------------------------------------------------------
// K2: warp-specialized recurrent kernel, 2 gate rows per thread.
//   A (warps 0-3,  tid 0-99):    W_hh0 rows (o, o+100) -> Z0 in ph1
//   B (warps 4-7,  tid 128-227): W_ih1 rows -> z1 in ph3;
//                  whole warps 4-7: head(t-1) + cp.async prefetch in ph1
//   C (warps 8-11, tid 256-355): W_hh1 rows -> p2 in ph1 (parallel with Z0)
// Each h LDS.128 feeds 2 dot products (rows o and o+100): LDS halved.
// pd term applied inside act0 (wpd_s) so the head lags one step.
// ---------------------------------------------------------------------------
// dynamic SMEM layout (floats):
//   P0 @0 (5600) | P1 @5600 | p2s @11200 | h0s @16800 (1456) | h1s @18256
//   w1T @19712 (676 u64 = 1352) | pd_s @21064 (28) | wpd_s @21092 (200)
//   b1s @21292 (25) | w2s @21317 (25) | b2 @21342
#define SM_FLOATS 21344

__global__ __launch_bounds__(NT, 1) void rec_kernel(
    const float* __restrict__ w_ih0, const float* __restrict__ w_hh0,
    const float* __restrict__ w_ih1, const float* __restrict__ w_hh1,
    const float* __restrict__ b_ih1, const float* __restrict__ b_hh1,
    const float* __restrict__ w1,    const float* __restrict__ b1,
    const float* __restrict__ w2,    const float* __restrict__ b2,
    float* __restrict__ out)
{
    extern __shared__ __align__(16) float sm[];
    float* P0   = sm;
    float* P1   = sm + 5600;
    float* p2s  = sm + 11200;
    float* h0s  = sm + 16800;
    float* h1s  = sm + 18256;
    u64*   w1T  = (u64*)(sm + 19712);
    float* pd_s = sm + 21064;
    float* wpd_s= sm + 21092;
    float* b1s  = sm + 21292;
    float* w2s  = sm + 21317;
    float* b2sp = sm + 21342;

    const int tid  = threadIdx.x;
    const int wid  = tid >> 5;
    const int lane = tid & 31;
    const int b0   = blockIdx.x * BT;
    int bt = B_TOT - b0; if (bt > BT) bt = BT;     // 28 or 8 (even)

    // role: 0=A(W_hh0), 1=B(W_ih1), 2=C(W_hh1), 3=none. o in [0,100).
    int role = 3, o = 0;
    if (tid < 100)                    { role = 0; o = tid; }
    else if (tid >= 128 && tid < 228) { role = 1; o = tid - 128; }
    else if (tid >= 256 && tid < 356) { role = 2; o = tid - 256; }

    // two weight rows (o and o+100), 25 u64 each, exact (no padding)
    u64 wr0[25], wr1[25];
    float bias1a = 0.0f, bias1b = 0.0f;
    if (role != 3) {
        const float* base = (role == 0) ? w_hh0 : (role == 1) ? w_ih1 : w_hh1;
        const float* ra = base + o * 50;
        const float* rb = base + (o + 100) * 50;
#pragma unroll
        for (int q = 0; q < 25; q++) {
            wr0[q] = pack2(ra[2 * q], ra[2 * q + 1]);
            wr1[q] = pack2(rb[2 * q], rb[2 * q + 1]);
        }
        if (role == 0) {
            wpd_s[o]       = w_ih0[o * 35 + 34];
            wpd_s[o + 100] = w_ih0[(o + 100) * 35 + 34];
        } else if (role == 1) {
            bias1a = b_ih1[o] + b_hh1[o];
            bias1b = b_ih1[o + 100] + b_hh1[o + 100];
        }
    }

    for (int i = tid; i < BT * 52; i += NT) { h0s[i] = 0.0f; h1s[i] = 0.0f; }
    for (int i = tid; i < 676; i += NT) {
        int uu = i / 26, j = i - uu * 26;
        w1T[i] = (j < 25 && uu < 25) ? pack2(w1[j * 50 + 2 * uu], w1[j * 50 + 2 * uu + 1]) : 0ull;
    }
    if (tid < 25) { b1s[tid] = b1[tid]; w2s[tid] = w2[tid]; }
    if (tid < BT) pd_s[tid] = 0.0f;
    if (tid == 0) b2sp[0] = b2[0];
    float c0r[4], c1r[4];
#pragma unroll
    for (int n = 0; n < 4; n++) { c0r[n] = 0.0f; c1r[n] = 0.0f; }

    const int nact = bt * 50;
    const int nz4  = bt * 50;   // float4 count of a pre0 tile
    const uint32_t smP0 = (uint32_t)__cvta_generic_to_shared(P0);
    const uint32_t smP1 = (uint32_t)__cvta_generic_to_shared(P1);

    // prologue: fetch pre0(t=0) into P0
    {
        const float4* psrc = (const float4*)(g_pre0 + (size_t)b0 * 200);
        for (int idx = tid; idx < nz4; idx += NT)
            cpasync16(smP0 + idx * 16, psrc + idx);
        cpcommit(); cpwait0();
    }
    __syncthreads();

    // 2-rows x 2-batches matvec macro body (12 ulonglong2 + 1 u64 tail = 50 floats)
#define MATVEC2x2(HS, W0, W1, A00, A01, A10, A11, bb)                          \
    {                                                                          \
        const ulonglong2* hA = (const ulonglong2*)(HS + (bb) * 52);            \
        const ulonglong2* hB = (const ulonglong2*)(HS + ((bb) + 1) * 52);      \
        _Pragma("unroll")                                                      \
        for (int j = 0; j < 12; j++) {                                         \
            ulonglong2 vA = hA[j], vB = hB[j];                                 \
            A00 = ffma2(W0[2 * j],     vA.x, A00);                             \
            A01 = ffma2(W0[2 * j],     vB.x, A01);                             \
            A10 = ffma2(W1[2 * j],     vA.x, A10);                             \
            A11 = ffma2(W1[2 * j],     vB.x, A11);                             \
            A00 = ffma2(W0[2 * j + 1], vA.y, A00);                             \
            A01 = ffma2(W0[2 * j + 1], vB.y, A01);                             \
            A10 = ffma2(W1[2 * j + 1], vA.y, A10);                             \
            A11 = ffma2(W1[2 * j + 1], vB.y, A11);                             \
        }                                                                      \
        u64 tA = ((const u64*)(HS + (bb) * 52))[24];                           \
        u64 tB = ((const u64*)(HS + ((bb) + 1) * 52))[24];                     \
        A00 = ffma2(W0[24], tA, A00);                                          \
        A01 = ffma2(W0[24], tB, A01);                                          \
        A10 = ffma2(W1[24], tA, A10);                                          \
        A11 = ffma2(W1[24], tB, A11);                                          \
    }

    for (int t = 0; t < S_LEN; t++) {
        float* cur = (t & 1) ? P1 : P0;
        const uint32_t nxt = (t & 1) ? smP0 : smP1;

        // ---- ph1: A: Z0 | C: p2 | warps 4-7: head(t-1) + prefetch(t+1) ----
        if (role == 0) {
            for (int b = 0; b < bt; b += 2) {
                u64 a00 = 0ull, a01 = 0ull, a10 = 0ull, a11 = 0ull;
                MATVEC2x2(h0s, wr0, wr1, a00, a01, a10, a11, b);
                float2 f00 = unpack2(a00), f01 = unpack2(a01);
                float2 f10 = unpack2(a10), f11 = unpack2(a11);
                cur[b * 200 + o]             += f00.x + f00.y;
                cur[(b + 1) * 200 + o]       += f01.x + f01.y;
                cur[b * 200 + o + 100]       += f10.x + f10.y;
                cur[(b + 1) * 200 + o + 100] += f11.x + f11.y;
            }
        } else if (role == 2) {
            for (int b = 0; b < bt; b += 2) {
                u64 a00 = 0ull, a01 = 0ull, a10 = 0ull, a11 = 0ull;
                MATVEC2x2(h1s, wr0, wr1, a00, a01, a10, a11, b);
                float2 f00 = unpack2(a00), f01 = unpack2(a01);
                float2 f10 = unpack2(a10), f11 = unpack2(a11);
                p2s[b * 200 + o]             = f00.x + f00.y;
                p2s[(b + 1) * 200 + o]       = f01.x + f01.y;
                p2s[b * 200 + o + 100]       = f10.x + f10.y;
                p2s[(b + 1) * 200 + o + 100] = f11.x + f11.y;
            }
        } else if (wid >= 4 && wid < 8) {
            if (t > 0) {
                for (int b = wid - 4; b < bt; b += 4) {
                    float v = 0.0f;
                    if (lane < 25) {
                        const u64* hv = (const u64*)(h1s + b * 52);
                        u64 acc = 0ull;
#pragma unroll
                        for (int uu = 0; uu < 25; uu++)
                            acc = ffma2(w1T[uu * 26 + lane], hv[uu], acc);
                        float2 f = unpack2(acc);
                        v = w2s[lane] * fmaxf(f.x + f.y + b1s[lane], 0.0f);
                    }
#pragma unroll
                    for (int k = 16; k > 0; k >>= 1) v += __shfl_xor_sync(0xFFFFFFFFu, v, k);
                    if (lane == 0) {
                        float nd = pd_s[b] + 0.2f * tanha(v + b2sp[0]);
                        nd = fminf(fmaxf(nd, -1.5f), 1.5f);
                        pd_s[b] = nd;
                        out[(size_t)(b0 + b) * S_LEN + (t - 1)] = nd;
                    }
                }
            }
            if (t + 1 < S_LEN) {
                const float4* psrc = (const float4*)(g_pre0 + ((size_t)(t + 1) * B_TOT + b0) * 200);
                for (int idx = tid - 128; idx < nz4; idx += 128)
                    cpasync16(nxt + idx * 16, psrc + idx);
            }
            cpcommit();
        }
        __syncthreads();

        // ---- act0: adds wpd*pd(t-1) term here ----
#pragma unroll
        for (int n = 0; n < 4; n++) {
            int idx = tid + n * NT;
            if (idx < nact) {
                int b = idx / 50, u = idx - b * 50;
                const float* zr = cur + b * 200;
                float pdb = pd_s[b];
                float iv = zr[u]       + wpd_s[u]       * pdb;
                float fv = zr[u + 50]  + wpd_s[u + 50]  * pdb;
                float gv = zr[u + 100] + wpd_s[u + 100] * pdb;
                float ov = zr[u + 150] + wpd_s[u + 150] * pdb;
                float c = sigf(fv) * c0r[n] + sigf(iv) * tanha(gv);
                c0r[n] = c;
                h0s[b * 52 + u] = sigf(ov) * tanha(c);
            }
        }
        __syncthreads();

        // ---- ph3: B: z1 = bias1 + Wih1*h0new + p2 ----
        if (role == 1) {
            for (int b = 0; b < bt; b += 2) {
                u64 a00 = 0ull, a01 = 0ull, a10 = 0ull, a11 = 0ull;
                MATVEC2x2(h0s, wr0, wr1, a00, a01, a10, a11, b);
                float2 f00 = unpack2(a00), f01 = unpack2(a01);
                float2 f10 = unpack2(a10), f11 = unpack2(a11);
                cur[b * 200 + o]             = bias1a + f00.x + f00.y + p2s[b * 200 + o];
                cur[(b + 1) * 200 + o]       = bias1a + f01.x + f01.y + p2s[(b + 1) * 200 + o];
                cur[b * 200 + o + 100]       = bias1b + f10.x + f10.y + p2s[b * 200 + o + 100];
                cur[(b + 1) * 200 + o + 100] = bias1b + f11.x + f11.y + p2s[(b + 1) * 200 + o + 100];
            }
        }
        __syncthreads();

        // ---- act1 ----
#pragma unroll
        for (int n = 0; n < 4; n++) {
            int idx = tid + n * NT;
            if (idx < nact) {
                int b = idx / 50, u = idx - b * 50;
                const float* zr = cur + b * 200;
                float iv = zr[u], fv = zr[u + 50], gv = zr[u + 100], ov = zr[u + 150];
                float c = sigf(fv) * c1r[n] + sigf(iv) * tanha(gv);
                c1r[n] = c;
                h1s[b * 52 + u] = sigf(ov) * tanha(c);
            }
        }
        cpwait0();          // prefetch must land before ph1(t+1) reads it
        __syncthreads();
    }

    // ---- epilogue: head for t = S_LEN-1 ----
    if (wid >= 4 && wid < 8) {
        for (int b = wid - 4; b < bt; b += 4) {
            float v = 0.0f;
            if (lane < 25) {
                const u64* hv = (const u64*)(h1s + b * 52);
                u64 acc = 0ull;
#pragma unroll
                for (int uu = 0; uu < 25; uu++)
                    acc = ffma2(w1T[uu * 26 + lane], hv[uu], acc);
                float2 f = unpack2(acc);
                v = w2s[lane] * fmaxf(f.x + f.y + b1s[lane], 0.0f);
            }
#pragma unroll
            for (int k = 16; k > 0; k >>= 1) v += __shfl_xor_sync(0xFFFFFFFFu, v, k);
            if (lane == 0) {
                float nd = pd_s[b] + 0.2f * tanha(v + b2sp[0]);
                nd = fminf(fmaxf(nd, -1.5f), 1.5f);
                out[(size_t)(b0 + b) * S_LEN + (S_LEN - 1)] = nd;
            }
        }
    }
}

// ---------------------------------------------------------------------------
extern "C" void kernel_launch(void* const* d_in, const int* in_sizes, int n_in,
                              void* d_out, int out_size) {
    const float* features = (const float*)d_in[0];
    const float* w_ih0    = (const float*)d_in[1];
    const float* w_hh0    = (const float*)d_in[2];
    const float* b_ih0    = (const float*)d_in[3];
    const float* b_hh0    = (const float*)d_in[4];
    const float* w_ih1    = (const float*)d_in[5];
    const float* w_hh1    = (const float*)d_in[6];
    const float* b_ih1    = (const float*)d_in[7];
    const float* b_hh1    = (const float*)d_in[8];
    const float* w1       = (const float*)d_in[9];
    const float* b1       = (const float*)d_in[10];
    const float* w2       = (const float*)d_in[11];
    const float* b2       = (const float*)d_in[12];
    float* out = (float*)d_out;

    static bool attr_set = false;
    if (!attr_set) {
        cudaFuncSetAttribute(rec_kernel, cudaFuncAttributeMaxDynamicSharedMemorySize,
                             SM_FLOATS * 4);
        attr_set = true;
    }

    pre0f_kernel<<<B_TOT, 256>>>(features, w_ih0, b_ih0, b_hh0);
    rec_kernel<<<(B_TOT + BT - 1) / BT, NT, SM_FLOATS * 4>>>(
        w_ih0, w_hh0, w_ih1, w_hh1, b_ih1, b_hh1, w1, b1, w2, b2, out);
}

// round 11
// speedup vs baseline: 1.3290x; 1.0063x over previous
#include <cuda_runtime.h>
#include <cstdint>

// ---------------------------------------------------------------------------
// HybridSigLSTM: rolling signature + 2-layer LSTM(H=50) + MLP head + pd clip
// B=4096, S=256, DIN=4, WIN=5, D_AUG=5, SIG=30, COMB=35, GATES=4*50=200
// ---------------------------------------------------------------------------

#define B_TOT 4096
#define S_LEN 256
#define GATES 200
#define BT    28      // batch elements per CTA in recurrent kernel
#define NT    384     // threads in recurrent kernel (12 warps)

typedef unsigned long long u64;

// scratch (device global: allocation-free rule)
__device__ float g_pre0[(size_t)B_TOT * S_LEN * 200];  // [t][b][o]

// ---------------- helpers ----------------
__device__ __forceinline__ u64 ffma2(u64 a, u64 b, u64 c) {
    u64 d;
    asm("fma.rn.f32x2 %0, %1, %2, %3;" : "=l"(d) : "l"(a), "l"(b), "l"(c));
    return d;
}
__device__ __forceinline__ u64 pack2(float a, float b) {
    u64 r;
    asm("mov.b64 %0, {%1, %2};" : "=l"(r) : "f"(a), "f"(b));
    return r;
}
__device__ __forceinline__ float2 unpack2(u64 v) {
    float2 f;
    asm("mov.b64 {%0, %1}, %2;" : "=f"(f.x), "=f"(f.y) : "l"(v));
    return f;
}
__device__ __forceinline__ float ex2f(float x) {
    float y; asm("ex2.approx.f32 %0, %1;" : "=f"(y) : "f"(x)); return y;
}
__device__ __forceinline__ float rcpf(float x) {
    float y; asm("rcp.approx.f32 %0, %1;" : "=f"(y) : "f"(x)); return y;
}
__device__ __forceinline__ float sigf(float x) {
    return rcpf(1.0f + ex2f(-1.4426950408889634f * x));
}
__device__ __forceinline__ float tanha(float x) {
    return 2.0f * rcpf(1.0f + ex2f(-2.8853900817779268f * x)) - 1.0f;
}
__device__ __forceinline__ void cpasync16(uint32_t saddr, const void* gptr) {
    asm volatile("cp.async.cg.shared.global [%0], [%1], 16;" :: "r"(saddr), "l"(gptr));
}
__device__ __forceinline__ void cpcommit() {
    asm volatile("cp.async.commit_group;" ::: "memory");
}
__device__ __forceinline__ void cpwait0() {
    asm volatile("cp.async.wait_group 0;" ::: "memory");
}

// ---------------------------------------------------------------------------
// K1: fused signature + input projection. One CTA = full sequence of one b.
// ---------------------------------------------------------------------------
__global__ __launch_bounds__(256) void pre0f_kernel(const float* __restrict__ features,
                                                    const float* __restrict__ w_ih0,
                                                    const float* __restrict__ b_ih0,
                                                    const float* __restrict__ b_hh0) {
    __shared__ __align__(16) float4 sf[260];         // raw feature window (t-4..t+255)
    __shared__ __align__(16) float xs[256][36];
    const int tid = threadIdx.x;
    const int b   = blockIdx.x;

    for (int i = tid; i < 260; i += 256) {
        int gi = i - 4; if (gi < 0) gi = 0;
        sf[i] = __ldg((const float4*)features + (size_t)b * S_LEN + gi);
    }

    u64 wp[17];
    float bias = 0.0f;
    if (tid < GATES) {
        const float* wr = w_ih0 + tid * 35;
#pragma unroll
        for (int j = 0; j < 17; j++) wp[j] = pack2(wr[2 * j], wr[2 * j + 1]);
        bias = b_ih0[tid] + b_hh0[tid];
    }
    __syncthreads();

    {   // every thread computes sig features for row t = tid
        const int t = tid;
        float a[5][5];
#pragma unroll
        for (int k = 0; k < 5; k++) {
            int gi = t + k - 4;
            int idx = gi < 0 ? 0 : gi;
            float4 fv = sf[t + k];
            a[k][0] = (float)idx * (1.0f / 255.0f);
            a[k][1] = fv.x; a[k][2] = fv.y; a[k][3] = fv.z; a[k][4] = fv.w;
        }
        float* x = xs[t];
        x[0] = a[4][1]; x[1] = a[4][2]; x[2] = a[4][3]; x[3] = a[4][4];
#pragma unroll
        for (int i = 0; i < 5; i++) x[4 + i] = a[4][i] - a[0][i];
#pragma unroll
        for (int i = 0; i < 5; i++) {
#pragma unroll
            for (int j = 0; j < 5; j++) {
                float s = 0.0f;
#pragma unroll
                for (int k = 0; k < 4; k++) s += (a[k + 1][i] - a[k][i]) * a[k][j];
                x[9 + i * 5 + j] = s;
            }
        }
        x[34] = 0.0f; x[35] = 0.0f;
    }
    __syncthreads();

    if (tid < GATES) {
        for (int r = 0; r < 256; r += 2) {
            const ulonglong2* xA = (const ulonglong2*)&xs[r][0];
            const ulonglong2* xB = (const ulonglong2*)&xs[r + 1][0];
            u64 aA = 0ull, aB = 0ull;
#pragma unroll
            for (int q = 0; q < 8; q++) {
                ulonglong2 vA = xA[q], vB = xB[q];
                aA = ffma2(wp[2 * q],     vA.x, aA);
                aB = ffma2(wp[2 * q],     vB.x, aB);
                aA = ffma2(wp[2 * q + 1], vA.y, aA);
                aB = ffma2(wp[2 * q + 1], vB.y, aB);
            }
            u64 tA = ((const u64*)&xs[r][0])[16];
            u64 tB = ((const u64*)&xs[r + 1][0])[16];
            aA = ffma2(wp[16], tA, aA);
            aB = ffma2(wp[16], tB, aB);
            float2 fA = unpack2(aA), fB = unpack2(aB);
            size_t ia = ((size_t)r       * B_TOT + b) * 200 + tid;   // [t][b][o]
            size_t ib = ((size_t)(r + 1) * B_TOT + b) * 200 + tid;
            g_pre0[ia] = fA.x + fA.y + bias;
            g_pre0[ib] = fB.x + fB.y + bias;
        }
    }
}

// ---------------------------------------------------------------------------
// K2: recurrent kernel with ALL THREE matvecs in one phase (3 warps/SMSP).
// Per step t:
//   act0(t):  h0 = lstm0(X=P(t) + wpd*pd(t-1))
//   M:  A (warps 0-3):  P(t+1) += W_hh0·h0(t)          [into Y]
//       B (warps 4-7):  z1p = bias1 + W_ih1·h0(t)      [into X, freed by act0]
//       C (warps 8-11): p2  = W_hh1·h1(t-1)            [into p2s]
//   act1(t):  h1 = lstm1(z1p + p2)
//   H:  warps 0-7: head(t) -> pd(t), out[t]
//       warps 8-11: cp.async prefetch P(t+2) -> X, commit+wait
// 2 gate rows per thread (o, o+100): each h LDS.128 feeds 2 dot products.
// ---------------------------------------------------------------------------
// dynamic SMEM layout (floats):
//   B0 @0 (5600) | B1 @5600 | p2s @11200 | h0s @16800 (1456) | h1s @18256
//   w1T @19712 (676 u64 = 1352) | pd_s @21064 (28) | wpd_s @21092 (200)
//   b1s @21292 (25) | w2s @21317 (25) | b2 @21342
#define SM_FLOATS 21344

__global__ __launch_bounds__(NT, 1) void rec_kernel(
    const float* __restrict__ w_ih0, const float* __restrict__ w_hh0,
    const float* __restrict__ w_ih1, const float* __restrict__ w_hh1,
    const float* __restrict__ b_ih1, const float* __restrict__ b_hh1,
    const float* __restrict__ w1,    const float* __restrict__ b1,
    const float* __restrict__ w2,    const float* __restrict__ b2,
    float* __restrict__ out)
{
    extern __shared__ __align__(16) float sm[];
    float* Bf0  = sm;
    float* Bf1  = sm + 5600;
    float* p2s  = sm + 11200;
    float* h0s  = sm + 16800;
    float* h1s  = sm + 18256;
    u64*   w1T  = (u64*)(sm + 19712);
    float* pd_s = sm + 21064;
    float* wpd_s= sm + 21092;
    float* b1s  = sm + 21292;
    float* w2s  = sm + 21317;
    float* b2sp = sm + 21342;

    const int tid  = threadIdx.x;
    const int wid  = tid >> 5;
    const int lane = tid & 31;
    const int b0   = blockIdx.x * BT;
    int bt = B_TOT - b0; if (bt > BT) bt = BT;     // 28 or 8 (even)

    // role: 0=A(W_hh0), 1=B(W_ih1), 2=C(W_hh1), 3=none. o in [0,100).
    int role = 3, o = 0;
    if (tid < 100)                    { role = 0; o = tid; }
    else if (tid >= 128 && tid < 228) { role = 1; o = tid - 128; }
    else if (tid >= 256 && tid < 356) { role = 2; o = tid - 256; }

    // two weight rows (o and o+100), 25 u64 each
    u64 wr0[25], wr1[25];
    float bias1a = 0.0f, bias1b = 0.0f;
    if (role != 3) {
        const float* base = (role == 0) ? w_hh0 : (role == 1) ? w_ih1 : w_hh1;
        const float* ra = base + o * 50;
        const float* rb = base + (o + 100) * 50;
#pragma unroll
        for (int q = 0; q < 25; q++) {
            wr0[q] = pack2(ra[2 * q], ra[2 * q + 1]);
            wr1[q] = pack2(rb[2 * q], rb[2 * q + 1]);
        }
        if (role == 0) {
            wpd_s[o]       = w_ih0[o * 35 + 34];
            wpd_s[o + 100] = w_ih0[(o + 100) * 35 + 34];
        } else if (role == 1) {
            bias1a = b_ih1[o] + b_hh1[o];
            bias1b = b_ih1[o + 100] + b_hh1[o + 100];
        }
    }

    for (int i = tid; i < BT * 52; i += NT) { h0s[i] = 0.0f; h1s[i] = 0.0f; }
    for (int i = tid; i < 676; i += NT) {
        int uu = i / 26, j = i - uu * 26;
        w1T[i] = (j < 25 && uu < 25) ? pack2(w1[j * 50 + 2 * uu], w1[j * 50 + 2 * uu + 1]) : 0ull;
    }
    if (tid < 25) { b1s[tid] = b1[tid]; w2s[tid] = w2[tid]; }
    if (tid < BT) pd_s[tid] = 0.0f;
    if (tid == 0) b2sp[0] = b2[0];
    float c0r[4], c1r[4];
#pragma unroll
    for (int n = 0; n < 4; n++) { c0r[n] = 0.0f; c1r[n] = 0.0f; }

    const int nact = bt * 50;
    const int nz4  = bt * 50;   // float4 count of a pre0 tile
    const uint32_t smB0 = (uint32_t)__cvta_generic_to_shared(Bf0);
    const uint32_t smB1 = (uint32_t)__cvta_generic_to_shared(Bf1);

    // prologue: fetch P(0) -> B0 and P(1) -> B1
    {
        const float4* p0 = (const float4*)(g_pre0 + (size_t)b0 * 200);
        const float4* p1 = (const float4*)(g_pre0 + ((size_t)1 * B_TOT + b0) * 200);
        for (int idx = tid; idx < nz4; idx += NT) {
            cpasync16(smB0 + idx * 16, p0 + idx);
            cpasync16(smB1 + idx * 16, p1 + idx);
        }
        cpcommit(); cpwait0();
    }
    __syncthreads();

    // 2-rows x 2-batches matvec body (12 ulonglong2 + 1 u64 tail = 50 floats)
#define MATVEC2x2(HS, W0, W1, A00, A01, A10, A11, bb)                          \
    {                                                                          \
        const ulonglong2* hA = (const ulonglong2*)(HS + (bb) * 52);            \
        const ulonglong2* hB = (const ulonglong2*)(HS + ((bb) + 1) * 52);      \
        _Pragma("unroll")                                                      \
        for (int j = 0; j < 12; j++) {                                         \
            ulonglong2 vA = hA[j], vB = hB[j];                                 \
            A00 = ffma2(W0[2 * j],     vA.x, A00);                             \
            A01 = ffma2(W0[2 * j],     vB.x, A01);                             \
            A10 = ffma2(W1[2 * j],     vA.x, A10);                             \
            A11 = ffma2(W1[2 * j],     vB.x, A11);                             \
            A00 = ffma2(W0[2 * j + 1], vA.y, A00);                             \
            A01 = ffma2(W0[2 * j + 1], vB.y, A01);                             \
            A10 = ffma2(W1[2 * j + 1], vA.y, A10);                             \
            A11 = ffma2(W1[2 * j + 1], vB.y, A11);                             \
        }                                                                      \
        u64 tA = ((const u64*)(HS + (bb) * 52))[24];                           \
        u64 tB = ((const u64*)(HS + ((bb) + 1) * 52))[24];                     \
        A00 = ffma2(W0[24], tA, A00);                                          \
        A01 = ffma2(W0[24], tB, A01);                                          \
        A10 = ffma2(W1[24], tA, A10);                                          \
        A11 = ffma2(W1[24], tB, A11);                                          \
    }

    for (int t = 0; t < S_LEN; t++) {
        float* X = (t & 1) ? Bf1 : Bf0;            // holds P(t) (+Z0 accum)
        float* Y = (t & 1) ? Bf0 : Bf1;            // holds P(t+1)
        const uint32_t Xsm = (t & 1) ? smB1 : smB0;

        // ---- act0(t): h0 = lstm0(X + wpd*pd) ----
#pragma unroll
        for (int n = 0; n < 4; n++) {
            int idx = tid + n * NT;
            if (idx < nact) {
                int b = idx / 50, u = idx - b * 50;
                const float* zr = X + b * 200;
                float pdb = pd_s[b];
                float iv = zr[u]       + wpd_s[u]       * pdb;
                float fv = zr[u + 50]  + wpd_s[u + 50]  * pdb;
                float gv = zr[u + 100] + wpd_s[u + 100] * pdb;
                float ov = zr[u + 150] + wpd_s[u + 150] * pdb;
                float c = sigf(fv) * c0r[n] + sigf(iv) * tanha(gv);
                c0r[n] = c;
                h0s[b * 52 + u] = sigf(ov) * tanha(c);
            }
        }
        __syncthreads();

        // ---- M: all three matvecs concurrent (3 warps/SMSP) ----
        if (role == 0) {
            if (t + 1 < S_LEN) {
                for (int b = 0; b < bt; b += 2) {
                    u64 a00 = 0ull, a01 = 0ull, a10 = 0ull, a11 = 0ull;
                    MATVEC2x2(h0s, wr0, wr1, a00, a01, a10, a11, b);
                    float2 f00 = unpack2(a00), f01 = unpack2(a01);
                    float2 f10 = unpack2(a10), f11 = unpack2(a11);
                    Y[b * 200 + o]             += f00.x + f00.y;
                    Y[(b + 1) * 200 + o]       += f01.x + f01.y;
                    Y[b * 200 + o + 100]       += f10.x + f10.y;
                    Y[(b + 1) * 200 + o + 100] += f11.x + f11.y;
                }
            }
        } else if (role == 1) {
            for (int b = 0; b < bt; b += 2) {
                u64 a00 = 0ull, a01 = 0ull, a10 = 0ull, a11 = 0ull;
                MATVEC2x2(h0s, wr0, wr1, a00, a01, a10, a11, b);
                float2 f00 = unpack2(a00), f01 = unpack2(a01);
                float2 f10 = unpack2(a10), f11 = unpack2(a11);
                X[b * 200 + o]             = bias1a + f00.x + f00.y;
                X[(b + 1) * 200 + o]       = bias1a + f01.x + f01.y;
                X[b * 200 + o + 100]       = bias1b + f10.x + f10.y;
                X[(b + 1) * 200 + o + 100] = bias1b + f11.x + f11.y;
            }
        } else if (role == 2) {
            for (int b = 0; b < bt; b += 2) {
                u64 a00 = 0ull, a01 = 0ull, a10 = 0ull, a11 = 0ull;
                MATVEC2x2(h1s, wr0, wr1, a00, a01, a10, a11, b);
                float2 f00 = unpack2(a00), f01 = unpack2(a01);
                float2 f10 = unpack2(a10), f11 = unpack2(a11);
                p2s[b * 200 + o]             = f00.x + f00.y;
                p2s[(b + 1) * 200 + o]       = f01.x + f01.y;
                p2s[b * 200 + o + 100]       = f10.x + f10.y;
                p2s[(b + 1) * 200 + o + 100] = f11.x + f11.y;
            }
        }
        __syncthreads();

        // ---- act1(t): h1 = lstm1(z1p + p2) ----
#pragma unroll
        for (int n = 0; n < 4; n++) {
            int idx = tid + n * NT;
            if (idx < nact) {
                int b = idx / 50, u = idx - b * 50;
                const float* zr = X + b * 200;
                const float* pr = p2s + b * 200;
                float iv = zr[u]       + pr[u];
                float fv = zr[u + 50]  + pr[u + 50];
                float gv = zr[u + 100] + pr[u + 100];
                float ov = zr[u + 150] + pr[u + 150];
                float c = sigf(fv) * c1r[n] + sigf(iv) * tanha(gv);
                c1r[n] = c;
                h1s[b * 52 + u] = sigf(ov) * tanha(c);
            }
        }
        __syncthreads();

        // ---- H: warps 0-7 head(t) | warps 8-11 prefetch P(t+2) -> X ----
        if (wid < 8) {
            for (int b = wid; b < bt; b += 8) {
                float v = 0.0f;
                if (lane < 25) {
                    const u64* hv = (const u64*)(h1s + b * 52);
                    u64 acc = 0ull;
#pragma unroll
                    for (int uu = 0; uu < 25; uu++)
                        acc = ffma2(w1T[uu * 26 + lane], hv[uu], acc);
                    float2 f = unpack2(acc);
                    v = w2s[lane] * fmaxf(f.x + f.y + b1s[lane], 0.0f);
                }
#pragma unroll
                for (int k = 16; k > 0; k >>= 1) v += __shfl_xor_sync(0xFFFFFFFFu, v, k);
                if (lane == 0) {
                    float nd = pd_s[b] + 0.2f * tanha(v + b2sp[0]);
                    nd = fminf(fmaxf(nd, -1.5f), 1.5f);
                    pd_s[b] = nd;
                    out[(size_t)(b0 + b) * S_LEN + t] = nd;
                }
            }
        } else {
            if (t + 2 < S_LEN) {
                const float4* psrc = (const float4*)(g_pre0 + ((size_t)(t + 2) * B_TOT + b0) * 200);
                for (int idx = tid - 256; idx < nz4; idx += 128)
                    cpasync16(Xsm + idx * 16, psrc + idx);
            }
            cpcommit();
            cpwait0();
        }
        __syncthreads();
    }
}

// ---------------------------------------------------------------------------
extern "C" void kernel_launch(void* const* d_in, const int* in_sizes, int n_in,
                              void* d_out, int out_size) {
    const float* features = (const float*)d_in[0];
    const float* w_ih0    = (const float*)d_in[1];
    const float* w_hh0    = (const float*)d_in[2];
    const float* b_ih0    = (const float*)d_in[3];
    const float* b_hh0    = (const float*)d_in[4];
    const float* w_ih1    = (const float*)d_in[5];
    const float* w_hh1    = (const float*)d_in[6];
    const float* b_ih1    = (const float*)d_in[7];
    const float* b_hh1    = (const float*)d_in[8];
    const float* w1       = (const float*)d_in[9];
    const float* b1       = (const float*)d_in[10];
    const float* w2       = (const float*)d_in[11];
    const float* b2       = (const float*)d_in[12];
    float* out = (float*)d_out;

    static bool attr_set = false;
    if (!attr_set) {
        cudaFuncSetAttribute(rec_kernel, cudaFuncAttributeMaxDynamicSharedMemorySize,
                             SM_FLOATS * 4);
        attr_set = true;
    }

    pre0f_kernel<<<B_TOT, 256>>>(features, w_ih0, b_ih0, b_hh0);
    rec_kernel<<<(B_TOT + BT - 1) / BT, NT, SM_FLOATS * 4>>>(
        w_ih0, w_hh0, w_ih1, w_hh1, b_ih1, b_hh1, w1, b1, w2, b2, out);
}

// round 12
// speedup vs baseline: 1.3661x; 1.0280x over previous
#include <cuda_runtime.h>
#include <cstdint>

// ---------------------------------------------------------------------------
// HybridSigLSTM: rolling signature + 2-layer LSTM(H=50) + MLP head + pd clip
// B=4096, S=256, DIN=4, WIN=5, D_AUG=5, SIG=30, COMB=35, GATES=4*50=200
// ---------------------------------------------------------------------------

#define B_TOT 4096
#define S_LEN 256
#define GATES 200
#define BT    28      // batch elements per CTA in recurrent kernel
#define NT    384     // threads in recurrent kernel (12 warps)

typedef unsigned long long u64;

// scratch (device global: allocation-free rule)
__device__ float g_pre0[(size_t)B_TOT * S_LEN * 200];  // [t][b][o]

// ---------------- helpers ----------------
__device__ __forceinline__ u64 ffma2(u64 a, u64 b, u64 c) {
    u64 d;
    asm("fma.rn.f32x2 %0, %1, %2, %3;" : "=l"(d) : "l"(a), "l"(b), "l"(c));
    return d;
}
__device__ __forceinline__ u64 pack2(float a, float b) {
    u64 r;
    asm("mov.b64 %0, {%1, %2};" : "=l"(r) : "f"(a), "f"(b));
    return r;
}
__device__ __forceinline__ float2 unpack2(u64 v) {
    float2 f;
    asm("mov.b64 {%0, %1}, %2;" : "=f"(f.x), "=f"(f.y) : "l"(v));
    return f;
}
__device__ __forceinline__ float ex2f(float x) {
    float y; asm("ex2.approx.f32 %0, %1;" : "=f"(y) : "f"(x)); return y;
}
__device__ __forceinline__ float rcpf(float x) {
    float y; asm("rcp.approx.f32 %0, %1;" : "=f"(y) : "f"(x)); return y;
}
__device__ __forceinline__ float sigf(float x) {
    return rcpf(1.0f + ex2f(-1.4426950408889634f * x));
}
__device__ __forceinline__ float tanha(float x) {
    return 2.0f * rcpf(1.0f + ex2f(-2.8853900817779268f * x)) - 1.0f;
}
__device__ __forceinline__ void cpasync16(uint32_t saddr, const void* gptr) {
    asm volatile("cp.async.cg.shared.global [%0], [%1], 16;" :: "r"(saddr), "l"(gptr));
}
__device__ __forceinline__ void cpcommit() {
    asm volatile("cp.async.commit_group;" ::: "memory");
}
__device__ __forceinline__ void cpwait0() {
    asm volatile("cp.async.wait_group 0;" ::: "memory");
}

// ---------------------------------------------------------------------------
// K1: fused signature + input projection. One CTA = full sequence of one b.
// ---------------------------------------------------------------------------
__global__ __launch_bounds__(256) void pre0f_kernel(const float* __restrict__ features,
                                                    const float* __restrict__ w_ih0,
                                                    const float* __restrict__ b_ih0,
                                                    const float* __restrict__ b_hh0) {
    __shared__ __align__(16) float4 sf[260];         // raw feature window (t-4..t+255)
    __shared__ __align__(16) float xs[256][36];
    const int tid = threadIdx.x;
    const int b   = blockIdx.x;

    for (int i = tid; i < 260; i += 256) {
        int gi = i - 4; if (gi < 0) gi = 0;
        sf[i] = __ldg((const float4*)features + (size_t)b * S_LEN + gi);
    }

    u64 wp[17];
    float bias = 0.0f;
    if (tid < GATES) {
        const float* wr = w_ih0 + tid * 35;
#pragma unroll
        for (int j = 0; j < 17; j++) wp[j] = pack2(wr[2 * j], wr[2 * j + 1]);
        bias = b_ih0[tid] + b_hh0[tid];
    }
    __syncthreads();

    {   // every thread computes sig features for row t = tid
        const int t = tid;
        float a[5][5];
#pragma unroll
        for (int k = 0; k < 5; k++) {
            int gi = t + k - 4;
            int idx = gi < 0 ? 0 : gi;
            float4 fv = sf[t + k];
            a[k][0] = (float)idx * (1.0f / 255.0f);
            a[k][1] = fv.x; a[k][2] = fv.y; a[k][3] = fv.z; a[k][4] = fv.w;
        }
        float* x = xs[t];
        x[0] = a[4][1]; x[1] = a[4][2]; x[2] = a[4][3]; x[3] = a[4][4];
#pragma unroll
        for (int i = 0; i < 5; i++) x[4 + i] = a[4][i] - a[0][i];
#pragma unroll
        for (int i = 0; i < 5; i++) {
#pragma unroll
            for (int j = 0; j < 5; j++) {
                float s = 0.0f;
#pragma unroll
                for (int k = 0; k < 4; k++) s += (a[k + 1][i] - a[k][i]) * a[k][j];
                x[9 + i * 5 + j] = s;
            }
        }
        x[34] = 0.0f; x[35] = 0.0f;
    }
    __syncthreads();

    if (tid < GATES) {
        for (int r = 0; r < 256; r += 2) {
            const ulonglong2* xA = (const ulonglong2*)&xs[r][0];
            const ulonglong2* xB = (const ulonglong2*)&xs[r + 1][0];
            u64 aA = 0ull, aB = 0ull;
#pragma unroll
            for (int q = 0; q < 8; q++) {
                ulonglong2 vA = xA[q], vB = xB[q];
                aA = ffma2(wp[2 * q],     vA.x, aA);
                aB = ffma2(wp[2 * q],     vB.x, aB);
                aA = ffma2(wp[2 * q + 1], vA.y, aA);
                aB = ffma2(wp[2 * q + 1], vB.y, aB);
            }
            u64 tA = ((const u64*)&xs[r][0])[16];
            u64 tB = ((const u64*)&xs[r + 1][0])[16];
            aA = ffma2(wp[16], tA, aA);
            aB = ffma2(wp[16], tB, aB);
            float2 fA = unpack2(aA), fB = unpack2(aB);
            size_t ia = ((size_t)r       * B_TOT + b) * 200 + tid;   // [t][b][o]
            size_t ib = ((size_t)(r + 1) * B_TOT + b) * 200 + tid;
            g_pre0[ia] = fA.x + fA.y + bias;
            g_pre0[ib] = fB.x + fB.y + bias;
        }
    }
}

// ---------------------------------------------------------------------------
// K2: recurrent kernel, three concurrent matvecs + deferred cp.async wait.
// Per step t:
//   act0(t);  [warps 8-11: cpwait0 for P(t+1)-buffer prefetch]  barrier
//   M:  A: P(t+1) += W_hh0·h0 | B: z1p = b+W_ih1·h0 -> X | C: p2 = W_hh1·h1
//   act1(t)
//   H:  warps 8-11 issue prefetch P(t+2)->X (no wait) then join head;
//       all 12 warps: head(t) -> pd(t), out[t]
// ---------------------------------------------------------------------------
// dynamic SMEM layout (floats):
//   B0 @0 (5600) | B1 @5600 | p2s @11200 | h0s @16800 (1456) | h1s @18256
//   w1T @19712 (676 u64 = 1352) | pd_s @21064 (28) | wpd_s @21092 (200)
//   b1s @21292 (25) | w2s @21317 (25) | b2 @21342
#define SM_FLOATS 21344

__global__ __launch_bounds__(NT, 1) void rec_kernel(
    const float* __restrict__ w_ih0, const float* __restrict__ w_hh0,
    const float* __restrict__ w_ih1, const float* __restrict__ w_hh1,
    const float* __restrict__ b_ih1, const float* __restrict__ b_hh1,
    const float* __restrict__ w1,    const float* __restrict__ b1,
    const float* __restrict__ w2,    const float* __restrict__ b2,
    float* __restrict__ out)
{
    extern __shared__ __align__(16) float sm[];
    float* Bf0  = sm;
    float* Bf1  = sm + 5600;
    float* p2s  = sm + 11200;
    float* h0s  = sm + 16800;
    float* h1s  = sm + 18256;
    u64*   w1T  = (u64*)(sm + 19712);
    float* pd_s = sm + 21064;
    float* wpd_s= sm + 21092;
    float* b1s  = sm + 21292;
    float* w2s  = sm + 21317;
    float* b2sp = sm + 21342;

    const int tid  = threadIdx.x;
    const int wid  = tid >> 5;
    const int lane = tid & 31;
    const int b0   = blockIdx.x * BT;
    int bt = B_TOT - b0; if (bt > BT) bt = BT;     // 28 or 8 (even)

    // role: 0=A(W_hh0), 1=B(W_ih1), 2=C(W_hh1), 3=none. o in [0,100).
    int role = 3, o = 0;
    if (tid < 100)                    { role = 0; o = tid; }
    else if (tid >= 128 && tid < 228) { role = 1; o = tid - 128; }
    else if (tid >= 256 && tid < 356) { role = 2; o = tid - 256; }

    // two weight rows (o and o+100), 25 u64 each
    u64 wr0[25], wr1[25];
    float bias1a = 0.0f, bias1b = 0.0f;
    if (role != 3) {
        const float* base = (role == 0) ? w_hh0 : (role == 1) ? w_ih1 : w_hh1;
        const float* ra = base + o * 50;
        const float* rb = base + (o + 100) * 50;
#pragma unroll
        for (int q = 0; q < 25; q++) {
            wr0[q] = pack2(ra[2 * q], ra[2 * q + 1]);
            wr1[q] = pack2(rb[2 * q], rb[2 * q + 1]);
        }
        if (role == 0) {
            wpd_s[o]       = w_ih0[o * 35 + 34];
            wpd_s[o + 100] = w_ih0[(o + 100) * 35 + 34];
        } else if (role == 1) {
            bias1a = b_ih1[o] + b_hh1[o];
            bias1b = b_ih1[o + 100] + b_hh1[o + 100];
        }
    }

    for (int i = tid; i < BT * 52; i += NT) { h0s[i] = 0.0f; h1s[i] = 0.0f; }
    for (int i = tid; i < 676; i += NT) {
        int uu = i / 26, j = i - uu * 26;
        w1T[i] = (j < 25 && uu < 25) ? pack2(w1[j * 50 + 2 * uu], w1[j * 50 + 2 * uu + 1]) : 0ull;
    }
    if (tid < 25) { b1s[tid] = b1[tid]; w2s[tid] = w2[tid]; }
    if (tid < BT) pd_s[tid] = 0.0f;
    if (tid == 0) b2sp[0] = b2[0];
    float c0r[4], c1r[4];
#pragma unroll
    for (int n = 0; n < 4; n++) { c0r[n] = 0.0f; c1r[n] = 0.0f; }

    const int nact = bt * 50;
    const int nz4  = bt * 50;   // float4 count of a pre0 tile
    const uint32_t smB0 = (uint32_t)__cvta_generic_to_shared(Bf0);
    const uint32_t smB1 = (uint32_t)__cvta_generic_to_shared(Bf1);

    // prologue: fetch P(0) -> B0 and P(1) -> B1
    {
        const float4* p0 = (const float4*)(g_pre0 + (size_t)b0 * 200);
        const float4* p1 = (const float4*)(g_pre0 + ((size_t)1 * B_TOT + b0) * 200);
        for (int idx = tid; idx < nz4; idx += NT) {
            cpasync16(smB0 + idx * 16, p0 + idx);
            cpasync16(smB1 + idx * 16, p1 + idx);
        }
        cpcommit(); cpwait0();
    }
    __syncthreads();

    // 2-rows x 2-batches matvec body (12 ulonglong2 + 1 u64 tail = 50 floats)
#define MATVEC2x2(HS, W0, W1, A00, A01, A10, A11, bb)                          \
    {                                                                          \
        const ulonglong2* hA = (const ulonglong2*)(HS + (bb) * 52);            \
        const ulonglong2* hB = (const ulonglong2*)(HS + ((bb) + 1) * 52);      \
        _Pragma("unroll")                                                      \
        for (int j = 0; j < 12; j++) {                                         \
            ulonglong2 vA = hA[j], vB = hB[j];                                 \
            A00 = ffma2(W0[2 * j],     vA.x, A00);                             \
            A01 = ffma2(W0[2 * j],     vB.x, A01);                             \
            A10 = ffma2(W1[2 * j],     vA.x, A10);                             \
            A11 = ffma2(W1[2 * j],     vB.x, A11);                             \
            A00 = ffma2(W0[2 * j + 1], vA.y, A00);                             \
            A01 = ffma2(W0[2 * j + 1], vB.y, A01);                             \
            A10 = ffma2(W1[2 * j + 1], vA.y, A10);                             \
            A11 = ffma2(W1[2 * j + 1], vB.y, A11);                             \
        }                                                                      \
        u64 tA = ((const u64*)(HS + (bb) * 52))[24];                           \
        u64 tB = ((const u64*)(HS + ((bb) + 1) * 52))[24];                     \
        A00 = ffma2(W0[24], tA, A00);                                          \
        A01 = ffma2(W0[24], tB, A01);                                          \
        A10 = ffma2(W1[24], tA, A10);                                          \
        A11 = ffma2(W1[24], tB, A11);                                          \
    }

    for (int t = 0; t < S_LEN; t++) {
        float* X = (t & 1) ? Bf1 : Bf0;            // holds P(t) (+Z0 accum)
        float* Y = (t & 1) ? Bf0 : Bf1;            // holds P(t+1)
        const uint32_t Xsm = (t & 1) ? smB1 : smB0;

        // ---- act0(t): h0 = lstm0(X + wpd*pd) ----
#pragma unroll
        for (int n = 0; n < 4; n++) {
            int idx = tid + n * NT;
            if (idx < nact) {
                int b = idx / 50, u = idx - b * 50;
                const float* zr = X + b * 200;
                float pdb = pd_s[b];
                float iv = zr[u]       + wpd_s[u]       * pdb;
                float fv = zr[u + 50]  + wpd_s[u + 50]  * pdb;
                float gv = zr[u + 100] + wpd_s[u + 100] * pdb;
                float ov = zr[u + 150] + wpd_s[u + 150] * pdb;
                float c = sigf(fv) * c0r[n] + sigf(iv) * tanha(gv);
                c0r[n] = c;
                h0s[b * 52 + u] = sigf(ov) * tanha(c);
            }
        }
        // deferred wait: prefetch of P(t+1)-buffer (issued in H(t-1)) must be
        // visible before role A accumulates into Y in the M phase below.
        if (wid >= 8) cpwait0();
        __syncthreads();

        // ---- M: all three matvecs concurrent (3 full warps/SMSP) ----
        if (role == 0) {
            if (t + 1 < S_LEN) {
                for (int b = 0; b < bt; b += 2) {
                    u64 a00 = 0ull, a01 = 0ull, a10 = 0ull, a11 = 0ull;
                    MATVEC2x2(h0s, wr0, wr1, a00, a01, a10, a11, b);
                    float2 f00 = unpack2(a00), f01 = unpack2(a01);
                    float2 f10 = unpack2(a10), f11 = unpack2(a11);
                    Y[b * 200 + o]             += f00.x + f00.y;
                    Y[(b + 1) * 200 + o]       += f01.x + f01.y;
                    Y[b * 200 + o + 100]       += f10.x + f10.y;
                    Y[(b + 1) * 200 + o + 100] += f11.x + f11.y;
                }
            }
        } else if (role == 1) {
            for (int b = 0; b < bt; b += 2) {
                u64 a00 = 0ull, a01 = 0ull, a10 = 0ull, a11 = 0ull;
                MATVEC2x2(h0s, wr0, wr1, a00, a01, a10, a11, b);
                float2 f00 = unpack2(a00), f01 = unpack2(a01);
                float2 f10 = unpack2(a10), f11 = unpack2(a11);
                X[b * 200 + o]             = bias1a + f00.x + f00.y;
                X[(b + 1) * 200 + o]       = bias1a + f01.x + f01.y;
                X[b * 200 + o + 100]       = bias1b + f10.x + f10.y;
                X[(b + 1) * 200 + o + 100] = bias1b + f11.x + f11.y;
            }
        } else if (role == 2) {
            for (int b = 0; b < bt; b += 2) {
                u64 a00 = 0ull, a01 = 0ull, a10 = 0ull, a11 = 0ull;
                MATVEC2x2(h1s, wr0, wr1, a00, a01, a10, a11, b);
                float2 f00 = unpack2(a00), f01 = unpack2(a01);
                float2 f10 = unpack2(a10), f11 = unpack2(a11);
                p2s[b * 200 + o]             = f00.x + f00.y;
                p2s[(b + 1) * 200 + o]       = f01.x + f01.y;
                p2s[b * 200 + o + 100]       = f10.x + f10.y;
                p2s[(b + 1) * 200 + o + 100] = f11.x + f11.y;
            }
        }
        __syncthreads();

        // ---- act1(t): h1 = lstm1(z1p + p2) ----
#pragma unroll
        for (int n = 0; n < 4; n++) {
            int idx = tid + n * NT;
            if (idx < nact) {
                int b = idx / 50, u = idx - b * 50;
                const float* zr = X + b * 200;
                const float* pr = p2s + b * 200;
                float iv = zr[u]       + pr[u];
                float fv = zr[u + 50]  + pr[u + 50];
                float gv = zr[u + 100] + pr[u + 100];
                float ov = zr[u + 150] + pr[u + 150];
                float c = sigf(fv) * c1r[n] + sigf(iv) * tanha(gv);
                c1r[n] = c;
                h1s[b * 52 + u] = sigf(ov) * tanha(c);
            }
        }
        __syncthreads();

        // ---- H: warps 8-11 issue prefetch P(t+2)->X (no wait), then ALL
        //         12 warps run head(t) on batches b = wid + 12*r ----
        if (wid >= 8) {
            if (t + 2 < S_LEN) {
                const float4* psrc = (const float4*)(g_pre0 + ((size_t)(t + 2) * B_TOT + b0) * 200);
                for (int idx = tid - 256; idx < nz4; idx += 128)
                    cpasync16(Xsm + idx * 16, psrc + idx);
            }
            cpcommit();
        }
        for (int b = wid; b < bt; b += 12) {
            float v = 0.0f;
            if (lane < 25) {
                const u64* hv = (const u64*)(h1s + b * 52);
                u64 acc0 = 0ull, acc1 = 0ull;
#pragma unroll
                for (int uu = 0; uu < 12; uu++) {
                    acc0 = ffma2(w1T[(2 * uu) * 26 + lane],     hv[2 * uu],     acc0);
                    acc1 = ffma2(w1T[(2 * uu + 1) * 26 + lane], hv[2 * uu + 1], acc1);
                }
                acc0 = ffma2(w1T[24 * 26 + lane], hv[24], acc0);
                float2 f0 = unpack2(acc0), f1 = unpack2(acc1);
                v = w2s[lane] * fmaxf(f0.x + f0.y + f1.x + f1.y + b1s[lane], 0.0f);
            }
#pragma unroll
            for (int k = 16; k > 0; k >>= 1) v += __shfl_xor_sync(0xFFFFFFFFu, v, k);
            if (lane == 0) {
                float nd = pd_s[b] + 0.2f * tanha(v + b2sp[0]);
                nd = fminf(fmaxf(nd, -1.5f), 1.5f);
                pd_s[b] = nd;
                out[(size_t)(b0 + b) * S_LEN + t] = nd;
            }
        }
        __syncthreads();
    }
}

// ---------------------------------------------------------------------------
extern "C" void kernel_launch(void* const* d_in, const int* in_sizes, int n_in,
                              void* d_out, int out_size) {
    const float* features = (const float*)d_in[0];
    const float* w_ih0    = (const float*)d_in[1];
    const float* w_hh0    = (const float*)d_in[2];
    const float* b_ih0    = (const float*)d_in[3];
    const float* b_hh0    = (const float*)d_in[4];
    const float* w_ih1    = (const float*)d_in[5];
    const float* w_hh1    = (const float*)d_in[6];
    const float* b_ih1    = (const float*)d_in[7];
    const float* b_hh1    = (const float*)d_in[8];
    const float* w1       = (const float*)d_in[9];
    const float* b1       = (const float*)d_in[10];
    const float* w2       = (const float*)d_in[11];
    const float* b2       = (const float*)d_in[12];
    float* out = (float*)d_out;

    static bool attr_set = false;
    if (!attr_set) {
        cudaFuncSetAttribute(rec_kernel, cudaFuncAttributeMaxDynamicSharedMemorySize,
                             SM_FLOATS * 4);
        attr_set = true;
    }

    pre0f_kernel<<<B_TOT, 256>>>(features, w_ih0, b_ih0, b_hh0);
    rec_kernel<<<(B_TOT + BT - 1) / BT, NT, SM_FLOATS * 4>>>(
        w_ih0, w_hh0, w_ih1, w_hh1, b_ih1, b_hh1, w1, b1, w2, b2, out);
}

// round 15
// speedup vs baseline: 1.4511x; 1.0622x over previous
#include <cuda_runtime.h>
#include <cstdint>

// ---------------------------------------------------------------------------
// HybridSigLSTM: rolling signature + 2-layer LSTM(H=50) + MLP head + pd clip
// B=4096, S=256, DIN=4, WIN=5, D_AUG=5, SIG=30, COMB=35, GATES=4*50=200
// ---------------------------------------------------------------------------

#define B_TOT 4096
#define S_LEN 256
#define GATES 200
#define BT    28      // batch elements per CTA in recurrent kernel
#define NT    384     // threads in recurrent kernel (12 warps)

typedef unsigned long long u64;

// scratch (device global: allocation-free rule)
__device__ float g_pre0[(size_t)B_TOT * S_LEN * 200];  // [t][b][o]

// ---------------- helpers ----------------
__device__ __forceinline__ u64 ffma2(u64 a, u64 b, u64 c) {
    u64 d;
    asm("fma.rn.f32x2 %0, %1, %2, %3;" : "=l"(d) : "l"(a), "l"(b), "l"(c));
    return d;
}
__device__ __forceinline__ u64 pack2(float a, float b) {
    u64 r;
    asm("mov.b64 %0, {%1, %2};" : "=l"(r) : "f"(a), "f"(b));
    return r;
}
__device__ __forceinline__ float2 unpack2(u64 v) {
    float2 f;
    asm("mov.b64 {%0, %1}, %2;" : "=f"(f.x), "=f"(f.y) : "l"(v));
    return f;
}
__device__ __forceinline__ float ex2f(float x) {
    float y; asm("ex2.approx.f32 %0, %1;" : "=f"(y) : "f"(x)); return y;
}
__device__ __forceinline__ float rcpf(float x) {
    float y; asm("rcp.approx.f32 %0, %1;" : "=f"(y) : "f"(x)); return y;
}
__device__ __forceinline__ float sigf(float x) {
    return rcpf(1.0f + ex2f(-1.4426950408889634f * x));
}
__device__ __forceinline__ float tanha(float x) {
    return 2.0f * rcpf(1.0f + ex2f(-2.8853900817779268f * x)) - 1.0f;
}
__device__ __forceinline__ void cpasync16(uint32_t saddr, const void* gptr) {
    asm volatile("cp.async.cg.shared.global [%0], [%1], 16;" :: "r"(saddr), "l"(gptr));
}
__device__ __forceinline__ void cpcommit() {
    asm volatile("cp.async.commit_group;" ::: "memory");
}
__device__ __forceinline__ void cpwait0() {
    asm volatile("cp.async.wait_group 0;" ::: "memory");
}

// ---------------------------------------------------------------------------
// K1: fused signature + input projection. One CTA = full sequence of one b.
// ---------------------------------------------------------------------------
__global__ __launch_bounds__(256) void pre0f_kernel(const float* __restrict__ features,
                                                    const float* __restrict__ w_ih0,
                                                    const float* __restrict__ b_ih0,
                                                    const float* __restrict__ b_hh0) {
    __shared__ __align__(16) float4 sf[260];         // raw feature window (t-4..t+255)
    __shared__ __align__(16) float xs[256][36];
    const int tid = threadIdx.x;
    const int b   = blockIdx.x;

    for (int i = tid; i < 260; i += 256) {
        int gi = i - 4; if (gi < 0) gi = 0;
        sf[i] = __ldg((const float4*)features + (size_t)b * S_LEN + gi);
    }

    u64 wp[17];
    float bias = 0.0f;
    if (tid < GATES) {
        const float* wr = w_ih0 + tid * 35;
#pragma unroll
        for (int j = 0; j < 17; j++) wp[j] = pack2(wr[2 * j], wr[2 * j + 1]);
        bias = b_ih0[tid] + b_hh0[tid];
    }
    __syncthreads();

    {   // every thread computes sig features for row t = tid
        const int t = tid;
        float a[5][5];
#pragma unroll
        for (int k = 0; k < 5; k++) {
            int gi = t + k - 4;
            int idx = gi < 0 ? 0 : gi;
            float4 fv = sf[t + k];
            a[k][0] = (float)idx * (1.0f / 255.0f);
            a[k][1] = fv.x; a[k][2] = fv.y; a[k][3] = fv.z; a[k][4] = fv.w;
        }
        float* x = xs[t];
        x[0] = a[4][1]; x[1] = a[4][2]; x[2] = a[4][3]; x[3] = a[4][4];
#pragma unroll
        for (int i = 0; i < 5; i++) x[4 + i] = a[4][i] - a[0][i];
#pragma unroll
        for (int i = 0; i < 5; i++) {
#pragma unroll
            for (int j = 0; j < 5; j++) {
                float s = 0.0f;
#pragma unroll
                for (int k = 0; k < 4; k++) s += (a[k + 1][i] - a[k][i]) * a[k][j];
                x[9 + i * 5 + j] = s;
            }
        }
        x[34] = 0.0f; x[35] = 0.0f;
    }
    __syncthreads();

    if (tid < GATES) {
        for (int r = 0; r < 256; r += 2) {
            const ulonglong2* xA = (const ulonglong2*)&xs[r][0];
            const ulonglong2* xB = (const ulonglong2*)&xs[r + 1][0];
            u64 aA = 0ull, aB = 0ull;
#pragma unroll
            for (int q = 0; q < 8; q++) {
                ulonglong2 vA = xA[q], vB = xB[q];
                aA = ffma2(wp[2 * q],     vA.x, aA);
                aB = ffma2(wp[2 * q],     vB.x, aB);
                aA = ffma2(wp[2 * q + 1], vA.y, aA);
                aB = ffma2(wp[2 * q + 1], vB.y, aB);
            }
            u64 tA = ((const u64*)&xs[r][0])[16];
            u64 tB = ((const u64*)&xs[r + 1][0])[16];
            aA = ffma2(wp[16], tA, aA);
            aB = ffma2(wp[16], tB, aB);
            float2 fA = unpack2(aA), fB = unpack2(aB);
            size_t ia = ((size_t)r       * B_TOT + b) * 200 + tid;   // [t][b][o]
            size_t ib = ((size_t)(r + 1) * B_TOT + b) * 200 + tid;
            g_pre0[ia] = fA.x + fA.y + bias;
            g_pre0[ib] = fB.x + fB.y + bias;
        }
    }
}

// ---------------------------------------------------------------------------
// K2: recurrent kernel — balanced full-lane matvec warps.
// 600 weight rows (Whh0->z0s, Wih1->X(+bias1), Whh1->p2s) packed as:
//   warps 0-6  (tid 0-223):   2 rows/thread (rows 2*tid, 2*tid+1), stream 1400
//   warps 7-11 (tid 224-375): 1 row/thread  (row 448+tid-224),     stream 700
// All matvec threads run identical code; per-lane (weights, src h0s/h1s,
// dst, bias). act0 computes X + z0s + wpd*pd. 4 barriers/step.
// ---------------------------------------------------------------------------
// dynamic SMEM layout (floats):
//   B0 @0 (5600) | B1 @5600 | p2s @11200 | z0s @16800 | h0s @22400 (1456)
//   h1s @23856 (1456) | w1T @25312 (676 u64 = 1352) | pd_s @26664 (28)
//   wpd_s @26692 (200) | b1s @26892 (25) | w2s @26917 (25) | b2 @26942
#define SM_FLOATS 26944

__global__ __launch_bounds__(NT, 1) void rec_kernel(
    const float* __restrict__ w_ih0, const float* __restrict__ w_hh0,
    const float* __restrict__ w_ih1, const float* __restrict__ w_hh1,
    const float* __restrict__ b_ih1, const float* __restrict__ b_hh1,
    const float* __restrict__ w1,    const float* __restrict__ b1,
    const float* __restrict__ w2,    const float* __restrict__ b2,
    float* __restrict__ out)
{
    extern __shared__ __align__(16) float sm[];
    float* Bf0  = sm;
    float* Bf1  = sm + 5600;
    float* p2s  = sm + 11200;
    float* z0s  = sm + 16800;
    float* h0s  = sm + 22400;
    float* h1s  = sm + 23856;
    u64*   w1T  = (u64*)(sm + 25312);
    float* pd_s = sm + 26664;
    float* wpd_s= sm + 26692;
    float* b1s  = sm + 26892;
    float* w2s  = sm + 26917;
    float* b2sp = sm + 26942;

    const int tid  = threadIdx.x;
    const int wid  = tid >> 5;
    const int lane = tid & 31;
    const int b0   = blockIdx.x * BT;
    int bt = B_TOT - b0; if (bt > BT) bt = BT;     // 28 or 8 (mult of 4)

    // ---- row assignment (see header comment) ----
    const int nr   = (tid < 224) ? 2 : (tid < 376 ? 1 : 0);
    const int ridx = (tid < 224) ? 2 * tid : 448 + (tid - 224);   // global row idx
    const int mtx  = ridx / 200;            // 0=Whh0, 1=Wih1, 2=Whh1
    const int r0   = ridx - mtx * 200;      // local row (r1 = r0+1, same matrix)

    u64 wr0[25], wr1[25];
    float bias0 = 0.0f, bias1r = 0.0f;
    const float* srcp = (mtx == 2) ? h1s : h0s;
    float* dfix0 = (mtx == 0) ? (z0s + r0) : (p2s + r0);          // m==1 handled per-step
    float* dfix1 = (mtx == 0) ? (z0s + r0 + 1) : (p2s + r0 + 1);
    if (nr > 0) {
        const float* wbase = (mtx == 0) ? w_hh0 : (mtx == 1) ? w_ih1 : w_hh1;
        const float* ra = wbase + r0 * 50;
#pragma unroll
        for (int q = 0; q < 25; q++) wr0[q] = pack2(ra[2 * q], ra[2 * q + 1]);
        if (mtx == 1) bias0 = b_ih1[r0] + b_hh1[r0];
        if (nr == 2) {
            const float* rb = wbase + (r0 + 1) * 50;
#pragma unroll
            for (int q = 0; q < 25; q++) wr1[q] = pack2(rb[2 * q], rb[2 * q + 1]);
            if (mtx == 1) bias1r = b_ih1[r0 + 1] + b_hh1[r0 + 1];
        }
    }

    // ---- init shared state ----
    for (int i = tid; i < BT * 52; i += NT) { h0s[i] = 0.0f; h1s[i] = 0.0f; }
    for (int i = tid; i < BT * 200; i += NT) z0s[i] = 0.0f;
    for (int i = tid; i < 676; i += NT) {
        int uu = i / 26, j = i - uu * 26;
        w1T[i] = (j < 25 && uu < 25) ? pack2(w1[j * 50 + 2 * uu], w1[j * 50 + 2 * uu + 1]) : 0ull;
    }
    for (int i = tid; i < 200; i += NT) wpd_s[i] = w_ih0[i * 35 + 34];
    if (tid < 25) { b1s[tid] = b1[tid]; w2s[tid] = w2[tid]; }
    if (tid < BT) pd_s[tid] = 0.0f;
    if (tid == 0) b2sp[0] = b2[0];
    float c0r[4], c1r[4];
#pragma unroll
    for (int n = 0; n < 4; n++) { c0r[n] = 0.0f; c1r[n] = 0.0f; }

    const int nact = bt * 50;
    const int nz4  = bt * 50;   // float4 count of a pre0 tile
    const uint32_t smB0 = (uint32_t)__cvta_generic_to_shared(Bf0);
    const uint32_t smB1 = (uint32_t)__cvta_generic_to_shared(Bf1);

    // prologue: fetch P(0) -> B0 and P(1) -> B1
    {
        const float4* p0 = (const float4*)(g_pre0 + (size_t)b0 * 200);
        const float4* p1 = (const float4*)(g_pre0 + ((size_t)1 * B_TOT + b0) * 200);
        for (int idx = tid; idx < nz4; idx += NT) {
            cpasync16(smB0 + idx * 16, p0 + idx);
            cpasync16(smB1 + idx * 16, p1 + idx);
        }
        cpcommit(); cpwait0();
    }
    __syncthreads();

    for (int t = 0; t < S_LEN; t++) {
        float* X = (t & 1) ? Bf1 : Bf0;            // holds P(t); becomes z1p
        const uint32_t Xsm = (t & 1) ? smB1 : smB0;

        // ---- act0(t): h0 = lstm0(X + z0s + wpd*pd) ----
#pragma unroll
        for (int n = 0; n < 4; n++) {
            int idx = tid + n * NT;
            if (idx < nact) {
                int b = idx / 50, u = idx - b * 50;
                const float* zr = X + b * 200;
                const float* z0 = z0s + b * 200;
                float pdb = pd_s[b];
                float iv = zr[u]       + z0[u]       + wpd_s[u]       * pdb;
                float fv = zr[u + 50]  + z0[u + 50]  + wpd_s[u + 50]  * pdb;
                float gv = zr[u + 100] + z0[u + 100] + wpd_s[u + 100] * pdb;
                float ov = zr[u + 150] + z0[u + 150] + wpd_s[u + 150] * pdb;
                float c = sigf(fv) * c0r[n] + sigf(iv) * tanha(gv);
                c0r[n] = c;
                h0s[b * 52 + u] = sigf(ov) * tanha(c);
            }
        }
        // deferred wait: the P-buffer prefetch issued in H(t-1) must be visible
        // before act0(t+1); waiting here (one phase early) keeps it off the path.
        if (wid >= 8) cpwait0();
        __syncthreads();

        // ---- M: unified matvecs. z0s(t+1)=Whh0*h0 | z1p=b+Wih1*h0 -> X |
        //         p2=Whh1*h1(t-1). Full-lane warps, 2 stream lengths. ----
        if (nr == 2) {
            float* d0 = (mtx == 1) ? (X + r0)     : dfix0;
            float* d1 = (mtx == 1) ? (X + r0 + 1) : dfix1;
            for (int b = 0; b < bt; b += 2) {
                const ulonglong2* hA = (const ulonglong2*)(srcp + b * 52);
                const ulonglong2* hB = (const ulonglong2*)(srcp + (b + 1) * 52);
                u64 a00 = 0ull, a01 = 0ull, a10 = 0ull, a11 = 0ull;
#pragma unroll
                for (int j = 0; j < 12; j++) {
                    ulonglong2 vA = hA[j], vB = hB[j];
                    a00 = ffma2(wr0[2 * j],     vA.x, a00);
                    a01 = ffma2(wr0[2 * j],     vB.x, a01);
                    a10 = ffma2(wr1[2 * j],     vA.x, a10);
                    a11 = ffma2(wr1[2 * j],     vB.x, a11);
                    a00 = ffma2(wr0[2 * j + 1], vA.y, a00);
                    a01 = ffma2(wr0[2 * j + 1], vB.y, a01);
                    a10 = ffma2(wr1[2 * j + 1], vA.y, a10);
                    a11 = ffma2(wr1[2 * j + 1], vB.y, a11);
                }
                u64 tA = ((const u64*)(srcp + b * 52))[24];
                u64 tB = ((const u64*)(srcp + (b + 1) * 52))[24];
                a00 = ffma2(wr0[24], tA, a00);
                a01 = ffma2(wr0[24], tB, a01);
                a10 = ffma2(wr1[24], tA, a10);
                a11 = ffma2(wr1[24], tB, a11);
                float2 f00 = unpack2(a00), f01 = unpack2(a01);
                float2 f10 = unpack2(a10), f11 = unpack2(a11);
                d0[b * 200]       = bias0  + f00.x + f00.y;
                d0[(b + 1) * 200] = bias0  + f01.x + f01.y;
                d1[b * 200]       = bias1r + f10.x + f10.y;
                d1[(b + 1) * 200] = bias1r + f11.x + f11.y;
            }
        } else if (nr == 1) {
            float* d0 = dfix0;                     // rows 448-599 all -> p2s
            for (int b = 0; b < bt; b += 2) {
                const ulonglong2* hA = (const ulonglong2*)(srcp + b * 52);
                const ulonglong2* hB = (const ulonglong2*)(srcp + (b + 1) * 52);
                u64 a0 = 0ull, a1 = 0ull;
#pragma unroll
                for (int j = 0; j < 12; j++) {
                    ulonglong2 vA = hA[j], vB = hB[j];
                    a0 = ffma2(wr0[2 * j],     vA.x, a0);
                    a1 = ffma2(wr0[2 * j],     vB.x, a1);
                    a0 = ffma2(wr0[2 * j + 1], vA.y, a0);
                    a1 = ffma2(wr0[2 * j + 1], vB.y, a1);
                }
                u64 tA = ((const u64*)(srcp + b * 52))[24];
                u64 tB = ((const u64*)(srcp + (b + 1) * 52))[24];
                a0 = ffma2(wr0[24], tA, a0);
                a1 = ffma2(wr0[24], tB, a1);
                float2 f0 = unpack2(a0), f1 = unpack2(a1);
                d0[b * 200]       = f0.x + f0.y;
                d0[(b + 1) * 200] = f1.x + f1.y;
            }
        }
        __syncthreads();

        // ---- act1(t): h1 = lstm1(z1p + p2) ----
#pragma unroll
        for (int n = 0; n < 4; n++) {
            int idx = tid + n * NT;
            if (idx < nact) {
                int b = idx / 50, u = idx - b * 50;
                const float* zr = X + b * 200;
                const float* pr = p2s + b * 200;
                float iv = zr[u]       + pr[u];
                float fv = zr[u + 50]  + pr[u + 50];
                float gv = zr[u + 100] + pr[u + 100];
                float ov = zr[u + 150] + pr[u + 150];
                float c = sigf(fv) * c1r[n] + sigf(iv) * tanha(gv);
                c1r[n] = c;
                h1s[b * 52 + u] = sigf(ov) * tanha(c);
            }
        }
        __syncthreads();

        // ---- H: warps 8-11 issue prefetch P(t+2)->X (no wait), then ALL
        //         12 warps run head(t) on batches b = wid + 12*r ----
        if (wid >= 8) {
            if (t + 2 < S_LEN) {
                const float4* psrc = (const float4*)(g_pre0 + ((size_t)(t + 2) * B_TOT + b0) * 200);
                for (int idx = tid - 256; idx < nz4; idx += 128)
                    cpasync16(Xsm + idx * 16, psrc + idx);
            }
            cpcommit();
        }
        for (int b = wid; b < bt; b += 12) {
            float v = 0.0f;
            if (lane < 25) {
                const u64* hv = (const u64*)(h1s + b * 52);
                u64 acc0 = 0ull, acc1 = 0ull;
#pragma unroll
                for (int uu = 0; uu < 12; uu++) {
                    acc0 = ffma2(w1T[(2 * uu) * 26 + lane],     hv[2 * uu],     acc0);
                    acc1 = ffma2(w1T[(2 * uu + 1) * 26 + lane], hv[2 * uu + 1], acc1);
                }
                acc0 = ffma2(w1T[24 * 26 + lane], hv[24], acc0);
                float2 f0 = unpack2(acc0), f1 = unpack2(acc1);
                v = w2s[lane] * fmaxf(f0.x + f0.y + f1.x + f1.y + b1s[lane], 0.0f);
            }
#pragma unroll
            for (int k = 16; k > 0; k >>= 1) v += __shfl_xor_sync(0xFFFFFFFFu, v, k);
            if (lane == 0) {
                float nd = pd_s[b] + 0.2f * tanha(v + b2sp[0]);
                nd = fminf(fmaxf(nd, -1.5f), 1.5f);
                pd_s[b] = nd;
                out[(size_t)(b0 + b) * S_LEN + t] = nd;
            }
        }
        __syncthreads();
    }
}

// ---------------------------------------------------------------------------
extern "C" void kernel_launch(void* const* d_in, const int* in_sizes, int n_in,
                              void* d_out, int out_size) {
    const float* features = (const float*)d_in[0];
    const float* w_ih0    = (const float*)d_in[1];
    const float* w_hh0    = (const float*)d_in[2];
    const float* b_ih0    = (const float*)d_in[3];
    const float* b_hh0    = (const float*)d_in[4];
    const float* w_ih1    = (const float*)d_in[5];
    const float* w_hh1    = (const float*)d_in[6];
    const float* b_ih1    = (const float*)d_in[7];
    const float* b_hh1    = (const float*)d_in[8];
    const float* w1       = (const float*)d_in[9];
    const float* b1       = (const float*)d_in[10];
    const float* w2       = (const float*)d_in[11];
    const float* b2       = (const float*)d_in[12];
    float* out = (float*)d_out;

    static bool attr_set = false;
    if (!attr_set) {
        cudaFuncSetAttribute(rec_kernel, cudaFuncAttributeMaxDynamicSharedMemorySize,
                             SM_FLOATS * 4);
        attr_set = true;
    }

    pre0f_kernel<<<B_TOT, 256>>>(features, w_ih0, b_ih0, b_hh0);
    rec_kernel<<<(B_TOT + BT - 1) / BT, NT, SM_FLOATS * 4>>>(
        w_ih0, w_hh0, w_ih1, w_hh1, b_ih1, b_hh1, w1, b1, w2, b2, out);
}

// round 16
// speedup vs baseline: 1.4650x; 1.0096x over previous
#include <cuda_runtime.h>
#include <cstdint>

// ---------------------------------------------------------------------------
// HybridSigLSTM: rolling signature + 2-layer LSTM(H=50) + MLP head + pd clip
// B=4096, S=256, DIN=4, WIN=5, D_AUG=5, SIG=30, COMB=35, GATES=4*50=200
// ---------------------------------------------------------------------------

#define B_TOT 4096
#define S_LEN 256
#define GATES 200
#define BT    28      // batch elements per CTA in recurrent kernel
#define NT    384     // threads in recurrent kernel (12 warps)

typedef unsigned long long u64;

// scratch (device global: allocation-free rule)
__device__ float g_pre0[(size_t)B_TOT * S_LEN * 200];  // [t][b][o]

// ---------------- helpers ----------------
__device__ __forceinline__ u64 ffma2(u64 a, u64 b, u64 c) {
    u64 d;
    asm("fma.rn.f32x2 %0, %1, %2, %3;" : "=l"(d) : "l"(a), "l"(b), "l"(c));
    return d;
}
__device__ __forceinline__ u64 pack2(float a, float b) {
    u64 r;
    asm("mov.b64 %0, {%1, %2};" : "=l"(r) : "f"(a), "f"(b));
    return r;
}
__device__ __forceinline__ float2 unpack2(u64 v) {
    float2 f;
    asm("mov.b64 {%0, %1}, %2;" : "=f"(f.x), "=f"(f.y) : "l"(v));
    return f;
}
__device__ __forceinline__ float ex2f(float x) {
    float y; asm("ex2.approx.f32 %0, %1;" : "=f"(y) : "f"(x)); return y;
}
__device__ __forceinline__ float rcpf(float x) {
    float y; asm("rcp.approx.f32 %0, %1;" : "=f"(y) : "f"(x)); return y;
}
__device__ __forceinline__ float sigf(float x) {
    return rcpf(1.0f + ex2f(-1.4426950408889634f * x));
}
__device__ __forceinline__ float tanha(float x) {
    return 2.0f * rcpf(1.0f + ex2f(-2.8853900817779268f * x)) - 1.0f;
}
__device__ __forceinline__ void cpasync16(uint32_t saddr, const void* gptr) {
    asm volatile("cp.async.cg.shared.global [%0], [%1], 16;" :: "r"(saddr), "l"(gptr));
}
__device__ __forceinline__ void cpcommit() {
    asm volatile("cp.async.commit_group;" ::: "memory");
}
__device__ __forceinline__ void cpwait0() {
    asm volatile("cp.async.wait_group 0;" ::: "memory");
}

// ---------------------------------------------------------------------------
// K1: fused signature + input projection. One CTA = full sequence of one b.
// ---------------------------------------------------------------------------
__global__ __launch_bounds__(256) void pre0f_kernel(const float* __restrict__ features,
                                                    const float* __restrict__ w_ih0,
                                                    const float* __restrict__ b_ih0,
                                                    const float* __restrict__ b_hh0) {
    __shared__ __align__(16) float4 sf[260];         // raw feature window (t-4..t+255)
    __shared__ __align__(16) float xs[256][36];
    const int tid = threadIdx.x;
    const int b   = blockIdx.x;

    for (int i = tid; i < 260; i += 256) {
        int gi = i - 4; if (gi < 0) gi = 0;
        sf[i] = __ldg((const float4*)features + (size_t)b * S_LEN + gi);
    }

    u64 wp[17];
    float bias = 0.0f;
    if (tid < GATES) {
        const float* wr = w_ih0 + tid * 35;
#pragma unroll
        for (int j = 0; j < 17; j++) wp[j] = pack2(wr[2 * j], wr[2 * j + 1]);
        bias = b_ih0[tid] + b_hh0[tid];
    }
    __syncthreads();

    {   // every thread computes sig features for row t = tid
        const int t = tid;
        float a[5][5];
#pragma unroll
        for (int k = 0; k < 5; k++) {
            int gi = t + k - 4;
            int idx = gi < 0 ? 0 : gi;
            float4 fv = sf[t + k];
            a[k][0] = (float)idx * (1.0f / 255.0f);
            a[k][1] = fv.x; a[k][2] = fv.y; a[k][3] = fv.z; a[k][4] = fv.w;
        }
        float* x = xs[t];
        x[0] = a[4][1]; x[1] = a[4][2]; x[2] = a[4][3]; x[3] = a[4][4];
#pragma unroll
        for (int i = 0; i < 5; i++) x[4 + i] = a[4][i] - a[0][i];
#pragma unroll
        for (int i = 0; i < 5; i++) {
#pragma unroll
            for (int j = 0; j < 5; j++) {
                float s = 0.0f;
#pragma unroll
                for (int k = 0; k < 4; k++) s += (a[k + 1][i] - a[k][i]) * a[k][j];
                x[9 + i * 5 + j] = s;
            }
        }
        x[34] = 0.0f; x[35] = 0.0f;
    }
    __syncthreads();

    if (tid < GATES) {
        for (int r = 0; r < 256; r += 2) {
            const ulonglong2* xA = (const ulonglong2*)&xs[r][0];
            const ulonglong2* xB = (const ulonglong2*)&xs[r + 1][0];
            u64 aA = 0ull, aB = 0ull;
#pragma unroll
            for (int q = 0; q < 8; q++) {
                ulonglong2 vA = xA[q], vB = xB[q];
                aA = ffma2(wp[2 * q],     vA.x, aA);
                aB = ffma2(wp[2 * q],     vB.x, aB);
                aA = ffma2(wp[2 * q + 1], vA.y, aA);
                aB = ffma2(wp[2 * q + 1], vB.y, aB);
            }
            u64 tA = ((const u64*)&xs[r][0])[16];
            u64 tB = ((const u64*)&xs[r + 1][0])[16];
            aA = ffma2(wp[16], tA, aA);
            aB = ffma2(wp[16], tB, aB);
            float2 fA = unpack2(aA), fB = unpack2(aB);
            size_t ia = ((size_t)r       * B_TOT + b) * 200 + tid;   // [t][b][o]
            size_t ib = ((size_t)(r + 1) * B_TOT + b) * 200 + tid;
            g_pre0[ia] = fA.x + fA.y + bias;
            g_pre0[ib] = fB.x + fB.y + bias;
        }
    }
}

// ---------------------------------------------------------------------------
// K2: recurrent kernel — balanced full-lane matvec warps + low-L1 phases.
// 600 weight rows (Whh0->z0s, Wih1->X(+bias1), Whh1->p2s):
//   warps 0-6  (tid 0-223):   2 rows/thread (wrA=row 2tid, wrB=row 2tid+1)
//   warps 7-11 (tid 224-375): 1 row/thread  (wrA=row 448+tid-224)
// wrB for tid>=224 (lane<25) holds the w1 COLUMN for the head (register
// union: disjoint thread sets). Head runs on warps 7-11; prefetch on 0-3.
// Acts process (u,u+1) pairs with LDS.64/STS.64; M pairs stores via STS.64.
// ---------------------------------------------------------------------------
// dynamic SMEM layout (floats):
//   B0 @0 (5600) | B1 @5600 | p2s @11200 | z0s @16800 | h0s @22400 (1456)
//   h1s @23856 (1456) | pd_s @25312 (28) | wpd_s @25340 (200)
//   b1s @25540 (25) | w2s @25565 (25) | b2 @25590
#define SM_FLOATS 25592

__global__ __launch_bounds__(NT, 1) void rec_kernel(
    const float* __restrict__ w_ih0, const float* __restrict__ w_hh0,
    const float* __restrict__ w_ih1, const float* __restrict__ w_hh1,
    const float* __restrict__ b_ih1, const float* __restrict__ b_hh1,
    const float* __restrict__ w1,    const float* __restrict__ b1,
    const float* __restrict__ w2,    const float* __restrict__ b2,
    float* __restrict__ out)
{
    extern __shared__ __align__(16) float sm[];
    float* Bf0  = sm;
    float* Bf1  = sm + 5600;
    float* p2s  = sm + 11200;
    float* z0s  = sm + 16800;
    float* h0s  = sm + 22400;
    float* h1s  = sm + 23856;
    float* pd_s = sm + 25312;
    float* wpd_s= sm + 25340;
    float* b1s  = sm + 25540;
    float* w2s  = sm + 25565;
    float* b2sp = sm + 25590;

    const int tid  = threadIdx.x;
    const int wid  = tid >> 5;
    const int lane = tid & 31;
    const int b0   = blockIdx.x * BT;
    int bt = B_TOT - b0; if (bt > BT) bt = BT;     // 28 or 8 (even)

    // ---- row assignment ----
    const int nr   = (tid < 224) ? 2 : (tid < 376 ? 1 : 0);
    const int ridx = (tid < 224) ? 2 * tid : 448 + (tid - 224);   // global row idx
    const int mtx  = ridx / 200;            // 0=Whh0, 1=Wih1, 2=Whh1
    const int r0   = ridx - mtx * 200;      // local row

    u64 wrA[25], wrB[25];
    float bias0 = 0.0f, bias1r = 0.0f;
    const float* srcp = (mtx == 2) ? h1s : h0s;
    if (nr > 0) {
        const float* wbase = (mtx == 0) ? w_hh0 : (mtx == 1) ? w_ih1 : w_hh1;
        const float* ra = wbase + r0 * 50;
#pragma unroll
        for (int q = 0; q < 25; q++) wrA[q] = pack2(ra[2 * q], ra[2 * q + 1]);
        if (mtx == 1) bias0 = b_ih1[r0] + b_hh1[r0];
        if (nr == 2) {
            const float* rb = wbase + (r0 + 1) * 50;
#pragma unroll
            for (int q = 0; q < 25; q++) wrB[q] = pack2(rb[2 * q], rb[2 * q + 1]);
            if (mtx == 1) bias1r = b_ih1[r0 + 1] + b_hh1[r0 + 1];
        }
    }
    // head threads (warps 7-11, lane<25): wrB = w1 column for hidden unit `lane`
    if (tid >= 224 && lane < 25) {
        const float* wc = w1 + lane * 50;
#pragma unroll
        for (int q = 0; q < 25; q++) wrB[q] = pack2(wc[2 * q], wc[2 * q + 1]);
    }
    // paired-store destination (u64 units) for 2-row threads with fixed dst
    u64* du_fix = (u64*)((mtx == 0) ? z0s : p2s) + (r0 >> 1);

    // ---- init shared state ----
    for (int i = tid; i < BT * 52; i += NT) { h0s[i] = 0.0f; h1s[i] = 0.0f; }
    for (int i = tid; i < BT * 200; i += NT) z0s[i] = 0.0f;
    for (int i = tid; i < 200; i += NT) wpd_s[i] = w_ih0[i * 35 + 34];
    if (tid < 25) { b1s[tid] = b1[tid]; w2s[tid] = w2[tid]; }
    if (tid < BT) pd_s[tid] = 0.0f;
    if (tid == 0) b2sp[0] = b2[0];
    float c0r[4], c1r[4];
#pragma unroll
    for (int n = 0; n < 4; n++) { c0r[n] = 0.0f; c1r[n] = 0.0f; }

    const int nact2 = bt * 25;   // (u,u+1)-pair items per act phase
    const int nz4   = bt * 50;   // float4 count of a pre0 tile
    const uint32_t smB0 = (uint32_t)__cvta_generic_to_shared(Bf0);
    const uint32_t smB1 = (uint32_t)__cvta_generic_to_shared(Bf1);

    // prologue: fetch P(0) -> B0 and P(1) -> B1
    {
        const float4* p0 = (const float4*)(g_pre0 + (size_t)b0 * 200);
        const float4* p1 = (const float4*)(g_pre0 + ((size_t)1 * B_TOT + b0) * 200);
        for (int idx = tid; idx < nz4; idx += NT) {
            cpasync16(smB0 + idx * 16, p0 + idx);
            cpasync16(smB1 + idx * 16, p1 + idx);
        }
        cpcommit(); cpwait0();
    }
    __syncthreads();

    for (int t = 0; t < S_LEN; t++) {
        float* X = (t & 1) ? Bf1 : Bf0;            // holds P(t); becomes z1p
        const uint32_t Xsm = (t & 1) ? smB1 : smB0;

        // ---- act0(t): h0 = lstm0(X + z0s + wpd*pd), (u,u+1) pairs ----
#pragma unroll
        for (int n = 0; n < 2; n++) {
            int idx = tid + n * NT;
            if (idx < nact2) {
                int b = idx / 25, up = idx - b * 25;
                const u64* zr = (const u64*)(X + b * 200);
                const u64* z0 = (const u64*)(z0s + b * 200);
                const u64* wp = (const u64*)wpd_s;
                float pdb = pd_s[b];
                float2 zi = unpack2(zr[up]),      ai = unpack2(z0[up]),      wi = unpack2(wp[up]);
                float2 zf = unpack2(zr[up + 25]), af = unpack2(z0[up + 25]), wf = unpack2(wp[up + 25]);
                float2 zg = unpack2(zr[up + 50]), ag = unpack2(z0[up + 50]), wg = unpack2(wp[up + 50]);
                float2 zo = unpack2(zr[up + 75]), ao = unpack2(z0[up + 75]), wo = unpack2(wp[up + 75]);
                float ivx = zi.x + ai.x + wi.x * pdb, ivy = zi.y + ai.y + wi.y * pdb;
                float fvx = zf.x + af.x + wf.x * pdb, fvy = zf.y + af.y + wf.y * pdb;
                float gvx = zg.x + ag.x + wg.x * pdb, gvy = zg.y + ag.y + wg.y * pdb;
                float ovx = zo.x + ao.x + wo.x * pdb, ovy = zo.y + ao.y + wo.y * pdb;
                float cx = sigf(fvx) * c0r[2 * n]     + sigf(ivx) * tanha(gvx);
                float cy = sigf(fvy) * c0r[2 * n + 1] + sigf(ivy) * tanha(gvy);
                c0r[2 * n] = cx; c0r[2 * n + 1] = cy;
                ((u64*)(h0s + b * 52))[up] = pack2(sigf(ovx) * tanha(cx),
                                                   sigf(ovy) * tanha(cy));
            }
        }
        // deferred wait: prefetch issued in H(t-1) (by warps 0-3) lands before
        // act0(t+2) reads that buffer; waiting here keeps it off the path.
        if (wid < 4) cpwait0();
        __syncthreads();

        // ---- M: z0s(t+1)=Whh0*h0 | z1p=b+Wih1*h0 -> X | p2=Whh1*h1(t-1) ----
        if (nr == 2) {
            u64* du = (mtx == 1) ? ((u64*)X + (r0 >> 1)) : du_fix;
            for (int b = 0; b < bt; b += 2) {
                const ulonglong2* hA = (const ulonglong2*)(srcp + b * 52);
                const ulonglong2* hB = (const ulonglong2*)(srcp + (b + 1) * 52);
                u64 a00 = 0ull, a01 = 0ull, a10 = 0ull, a11 = 0ull;
#pragma unroll
                for (int j = 0; j < 12; j++) {
                    ulonglong2 vA = hA[j], vB = hB[j];
                    a00 = ffma2(wrA[2 * j],     vA.x, a00);
                    a01 = ffma2(wrA[2 * j],     vB.x, a01);
                    a10 = ffma2(wrB[2 * j],     vA.x, a10);
                    a11 = ffma2(wrB[2 * j],     vB.x, a11);
                    a00 = ffma2(wrA[2 * j + 1], vA.y, a00);
                    a01 = ffma2(wrA[2 * j + 1], vB.y, a01);
                    a10 = ffma2(wrB[2 * j + 1], vA.y, a10);
                    a11 = ffma2(wrB[2 * j + 1], vB.y, a11);
                }
                u64 tA = ((const u64*)(srcp + b * 52))[24];
                u64 tB = ((const u64*)(srcp + (b + 1) * 52))[24];
                a00 = ffma2(wrA[24], tA, a00);
                a01 = ffma2(wrA[24], tB, a01);
                a10 = ffma2(wrB[24], tA, a10);
                a11 = ffma2(wrB[24], tB, a11);
                float2 f00 = unpack2(a00), f01 = unpack2(a01);
                float2 f10 = unpack2(a10), f11 = unpack2(a11);
                du[b * 100]       = pack2(bias0 + f00.x + f00.y, bias1r + f10.x + f10.y);
                du[(b + 1) * 100] = pack2(bias0 + f01.x + f01.y, bias1r + f11.x + f11.y);
            }
        } else if (nr == 1) {
            float* d0 = p2s + r0;                  // rows 448-599 all -> p2s
            for (int b = 0; b < bt; b += 2) {
                const ulonglong2* hA = (const ulonglong2*)(srcp + b * 52);
                const ulonglong2* hB = (const ulonglong2*)(srcp + (b + 1) * 52);
                u64 a0 = 0ull, a1 = 0ull;
#pragma unroll
                for (int j = 0; j < 12; j++) {
                    ulonglong2 vA = hA[j], vB = hB[j];
                    a0 = ffma2(wrA[2 * j],     vA.x, a0);
                    a1 = ffma2(wrA[2 * j],     vB.x, a1);
                    a0 = ffma2(wrA[2 * j + 1], vA.y, a0);
                    a1 = ffma2(wrA[2 * j + 1], vB.y, a1);
                }
                u64 tA = ((const u64*)(srcp + b * 52))[24];
                u64 tB = ((const u64*)(srcp + (b + 1) * 52))[24];
                a0 = ffma2(wrA[24], tA, a0);
                a1 = ffma2(wrA[24], tB, a1);
                float2 f0 = unpack2(a0), f1 = unpack2(a1);
                d0[b * 200]       = f0.x + f0.y;
                d0[(b + 1) * 200] = f1.x + f1.y;
            }
        }
        __syncthreads();

        // ---- act1(t): h1 = lstm1(z1p + p2), (u,u+1) pairs ----
#pragma unroll
        for (int n = 0; n < 2; n++) {
            int idx = tid + n * NT;
            if (idx < nact2) {
                int b = idx / 25, up = idx - b * 25;
                const u64* zr = (const u64*)(X + b * 200);
                const u64* pr = (const u64*)(p2s + b * 200);
                float2 zi = unpack2(zr[up]),      pi = unpack2(pr[up]);
                float2 zf = unpack2(zr[up + 25]), pf = unpack2(pr[up + 25]);
                float2 zg = unpack2(zr[up + 50]), pg = unpack2(pr[up + 50]);
                float2 zo = unpack2(zr[up + 75]), po = unpack2(pr[up + 75]);
                float ivx = zi.x + pi.x, ivy = zi.y + pi.y;
                float fvx = zf.x + pf.x, fvy = zf.y + pf.y;
                float gvx = zg.x + pg.x, gvy = zg.y + pg.y;
                float ovx = zo.x + po.x, ovy = zo.y + po.y;
                float cx = sigf(fvx) * c1r[2 * n]     + sigf(ivx) * tanha(gvx);
                float cy = sigf(fvy) * c1r[2 * n + 1] + sigf(ivy) * tanha(gvy);
                c1r[2 * n] = cx; c1r[2 * n + 1] = cy;
                ((u64*)(h1s + b * 52))[up] = pack2(sigf(ovx) * tanha(cx),
                                                   sigf(ovy) * tanha(cy));
            }
        }
        __syncthreads();

        // ---- H: warps 0-3 issue prefetch P(t+2)->X (no wait);
        //         warps 7-11 run head(t) with w1 in registers (wrB) ----
        if (wid < 4) {
            if (t + 2 < S_LEN) {
                const float4* psrc = (const float4*)(g_pre0 + ((size_t)(t + 2) * B_TOT + b0) * 200);
                for (int idx = tid; idx < nz4; idx += 128)
                    cpasync16(Xsm + idx * 16, psrc + idx);
            }
            cpcommit();
        } else if (wid >= 7) {
            for (int b = wid - 7; b < bt; b += 5) {
                float v = 0.0f;
                if (lane < 25) {
                    const u64* hv = (const u64*)(h1s + b * 52);
                    u64 acc0 = 0ull, acc1 = 0ull;
#pragma unroll
                    for (int uu = 0; uu < 12; uu++) {
                        acc0 = ffma2(wrB[2 * uu],     hv[2 * uu],     acc0);
                        acc1 = ffma2(wrB[2 * uu + 1], hv[2 * uu + 1], acc1);
                    }
                    acc0 = ffma2(wrB[24], hv[24], acc0);
                    float2 f0 = unpack2(acc0), f1 = unpack2(acc1);
                    v = w2s[lane] * fmaxf(f0.x + f0.y + f1.x + f1.y + b1s[lane], 0.0f);
                }
#pragma unroll
                for (int k = 16; k > 0; k >>= 1) v += __shfl_xor_sync(0xFFFFFFFFu, v, k);
                if (lane == 0) {
                    float nd = pd_s[b] + 0.2f * tanha(v + b2sp[0]);
                    nd = fminf(fmaxf(nd, -1.5f), 1.5f);
                    pd_s[b] = nd;
                    out[(size_t)(b0 + b) * S_LEN + t] = nd;
                }
            }
        }
        __syncthreads();
    }
}

// ---------------------------------------------------------------------------
extern "C" void kernel_launch(void* const* d_in, const int* in_sizes, int n_in,
                              void* d_out, int out_size) {
    const float* features = (const float*)d_in[0];
    const float* w_ih0    = (const float*)d_in[1];
    const float* w_hh0    = (const float*)d_in[2];
    const float* b_ih0    = (const float*)d_in[3];
    const float* b_hh0    = (const float*)d_in[4];
    const float* w_ih1    = (const float*)d_in[5];
    const float* w_hh1    = (const float*)d_in[6];
    const float* b_ih1    = (const float*)d_in[7];
    const float* b_hh1    = (const float*)d_in[8];
    const float* w1       = (const float*)d_in[9];
    const float* b1       = (const float*)d_in[10];
    const float* w2       = (const float*)d_in[11];
    const float* b2       = (const float*)d_in[12];
    float* out = (float*)d_out;

    static bool attr_set = false;
    if (!attr_set) {
        cudaFuncSetAttribute(rec_kernel, cudaFuncAttributeMaxDynamicSharedMemorySize,
                             SM_FLOATS * 4);
        attr_set = true;
    }

    pre0f_kernel<<<B_TOT, 256>>>(features, w_ih0, b_ih0, b_hh0);
    rec_kernel<<<(B_TOT + BT - 1) / BT, NT, SM_FLOATS * 4>>>(
        w_ih0, w_hh0, w_ih1, w_hh1, b_ih1, b_hh1, w1, b1, w2, b2, out);
}